// round 11
// baseline (speedup 1.0000x reference)
#include <cuda_runtime.h>
#include <cuda_bf16.h>
#include <cstdint>

#define SEQ 2048
#define DIM 4096
#define NH  32
#define NKV 8
#define HD  128
#define QKVN 6144   // fused projection N (4096 q + 1024 k + 1024 v)

// ---------------- scratch (device globals: no allocation allowed) ----------------
__device__ float    g_qkv[(size_t)SEQ * QKVN];       // fused q|k|v (fp32)
__device__ float    g_att[(size_t)SEQ * DIM];        // attention out (rna-rounded)
__device__ float    g_xc[(size_t)SEQ * DIM];         // rna-rounded x
__device__ float    g_wqc[(size_t)DIM * DIM];        // rna-rounded wq
__device__ float    g_wkc[(size_t)1024 * DIM];       // rna-rounded wk
__device__ float    g_wvc[(size_t)1024 * DIM];       // rna-rounded wv
__device__ float    g_woc[(size_t)DIM * DIM];        // rna-rounded wo
__device__ uint32_t g_qh[(size_t)NH  * SEQ * 64];    // Q hi  bf16x2 (scaled, roped)
__device__ uint32_t g_ql[(size_t)NH  * SEQ * 64];    // Q lo  bf16x2
__device__ uint32_t g_kh[(size_t)NKV * SEQ * 64];    // K hi  bf16x2 (roped)
__device__ uint32_t g_kl[(size_t)NKV * SEQ * 64];    // K lo  bf16x2
__device__ float    g_vt[(size_t)NKV * HD * SEQ];    // V transposed [c][s], tf32

__device__ __forceinline__ uint32_t cvt_tf32(float x) {
    uint32_t r;
    asm("cvt.rna.tf32.f32 %0, %1;" : "=r"(r) : "f"(x));
    return r;
}
__device__ __forceinline__ float tf32f(float x) { return __uint_as_float(cvt_tf32(x)); }
__device__ __forceinline__ void ldm4(uint32_t* r, uint32_t addr) {
    asm volatile("ldmatrix.sync.aligned.m8n8.x4.shared.b16 {%0,%1,%2,%3}, [%4];"
                 : "=r"(r[0]), "=r"(r[1]), "=r"(r[2]), "=r"(r[3]) : "r"(addr));
}
__device__ __forceinline__ void mma8(float* c, const uint32_t* a, uint32_t b0, uint32_t b1) {
    asm volatile("mma.sync.aligned.m16n8k8.row.col.f32.tf32.tf32.f32 "
                 "{%0,%1,%2,%3}, {%4,%5,%6,%7}, {%8,%9}, {%0,%1,%2,%3};"
                 : "+f"(c[0]), "+f"(c[1]), "+f"(c[2]), "+f"(c[3])
                 : "r"(a[0]), "r"(a[1]), "r"(a[2]), "r"(a[3]), "r"(b0), "r"(b1));
}
__device__ __forceinline__ void mma16(float* c, const uint32_t* a, uint32_t b0, uint32_t b1) {
    asm volatile("mma.sync.aligned.m16n8k16.row.col.f32.bf16.bf16.f32 "
                 "{%0,%1,%2,%3}, {%4,%5,%6,%7}, {%8,%9}, {%0,%1,%2,%3};"
                 : "+f"(c[0]), "+f"(c[1]), "+f"(c[2]), "+f"(c[3])
                 : "r"(a[0]), "r"(a[1]), "r"(a[2]), "r"(a[3]), "r"(b0), "r"(b1));
}
__device__ __forceinline__ uint32_t pack2bf(float a, float b) {
    __nv_bfloat162 t = __floats2bfloat162_rn(a, b);
    return *(uint32_t*)&t;
}
__device__ __forceinline__ float bfhi(float a) {
    return __bfloat162float(__float2bfloat16(a));
}

// ---------------- prepass: rna-round fp32 to tf32 values ----------------
__global__ void cvt_rna(const float* __restrict__ in, float* __restrict__ out, int n4)
{
    int i = blockIdx.x * blockDim.x + threadIdx.x;
    if (i >= n4) return;
    float4 v = ((const float4*)in)[i];
    v.x = tf32f(v.x); v.y = tf32f(v.y); v.z = tf32f(v.z); v.w = tf32f(v.w);
    ((float4*)out)[i] = v;
}

// ---------------- TF32 NT GEMM: cp.async 3-stage, wide warp tile -----------------
// Block 128x256, BK=32, 256 threads (8 warps 2x4), warp tile 64x64.
// Inputs pre-rounded (rna). No register staging; no in-loop cvt.
#define SA 36
#define ASTG (128 * SA)
#define BSTG (256 * SA)
#define GSTG (ASTG + BSTG)              // words per stage (55296 B)
#define GSMEM_BYTES (3 * GSTG * 4)      // 165888

__global__ __launch_bounds__(256, 1) void gemm_tf32(const float* __restrict__ A,
                                                    const float* __restrict__ B0,
                                                    const float* __restrict__ B1,
                                                    const float* __restrict__ B2,
                                                    float* __restrict__ C,
                                                    int M, int outN, int K)
{
    extern __shared__ float sh[];
    int tid = threadIdx.x;
    int wid = tid >> 5, lane = tid & 31;
    int warp_m = wid >> 2, warp_n = wid & 3;
    int m0 = blockIdx.y * 128, n0 = blockIdx.x * 256;

    const float* Bsel;
    int nloc;
    if (n0 < DIM)                { Bsel = B0; nloc = n0; }
    else if (n0 < DIM + 1024)    { Bsel = B1; nloc = n0 - DIM; }
    else                         { Bsel = B2; nloc = n0 - DIM - 1024; }

    int lr = tid >> 3;          // 0..31
    int lc = (tid & 7) * 4;     // 0..28
    const float* Aq = A + (size_t)(m0 + lr) * K + lc;
    const float* Bq = Bsel + (size_t)(nloc + lr) * K + lc;

    uint32_t shbase = (uint32_t)__cvta_generic_to_shared(sh);
    uint32_t sdA = shbase + (uint32_t)((lr * SA + lc) << 2);
    uint32_t sdB = shbase + (uint32_t)((ASTG + lr * SA + lc) << 2);

    int la = lane & 15, ahi = lane >> 4;
    int rbv = (lane & 7) + ((lane >> 4) << 3), bhiv = (lane >> 3) & 1;
    uint32_t a_addr[4], b_addr[4];
#pragma unroll
    for (int mi = 0; mi < 4; mi++)
        a_addr[mi] = shbase + (uint32_t)(((warp_m * 64 + mi * 16 + la) * SA + ahi * 4) << 2);
#pragma unroll
    for (int nb = 0; nb < 4; nb++)
        b_addr[nb] = shbase + (uint32_t)((ASTG + (warp_n * 64 + nb * 16 + rbv) * SA + bhiv * 4) << 2);

    float acc[4][8][4];
#pragma unroll
    for (int mi = 0; mi < 4; mi++)
#pragma unroll
        for (int ni = 0; ni < 8; ni++)
#pragma unroll
            for (int t = 0; t < 4; t++) acc[mi][ni][t] = 0.0f;

    const int iters = K >> 5;

    auto issue = [&](int s, int k0) {
        uint32_t off = (uint32_t)(s * GSTG * 4);
#pragma unroll
        for (int rr = 0; rr < 4; rr++)
            asm volatile("cp.async.cg.shared.global [%0], [%1], 16;"
                         :: "r"(sdA + off + (uint32_t)(rr * 32 * SA * 4)),
                            "l"(Aq + (size_t)rr * 32 * K + k0));
#pragma unroll
        for (int rr = 0; rr < 8; rr++)
            asm volatile("cp.async.cg.shared.global [%0], [%1], 16;"
                         :: "r"(sdB + off + (uint32_t)(rr * 32 * SA * 4)),
                            "l"(Bq + (size_t)rr * 32 * K + k0));
    };

    issue(0, 0);  asm volatile("cp.async.commit_group;");
    issue(1, 32); asm volatile("cp.async.commit_group;");

    for (int it = 0; it < iters; ++it) {
        asm volatile("cp.async.wait_group 1;");
        __syncthreads();
        if (it + 2 < iters) issue((it + 2) % 3, (it + 2) << 5);
        asm volatile("cp.async.commit_group;");

        uint32_t boff = (uint32_t)((it % 3) * GSTG * 4);
#pragma unroll
        for (int ks = 0; ks < 4; ks++) {
            uint32_t af[4][4], bf[4][4];
#pragma unroll
            for (int mi = 0; mi < 4; mi++) ldm4(af[mi], a_addr[mi] + boff + ks * 32);
#pragma unroll
            for (int nb = 0; nb < 4; nb++) ldm4(bf[nb], b_addr[nb] + boff + ks * 32);
#pragma unroll
            for (int mi = 0; mi < 4; mi++)
#pragma unroll
                for (int nb = 0; nb < 4; nb++) {
                    mma8(acc[mi][2 * nb],     af[mi], bf[nb][0], bf[nb][1]);
                    mma8(acc[mi][2 * nb + 1], af[mi], bf[nb][2], bf[nb][3]);
                }
        }
    }

    int g = lane >> 2, tg = lane & 3;
#pragma unroll
    for (int mi = 0; mi < 4; mi++) {
#pragma unroll
        for (int ni = 0; ni < 8; ni++) {
            int row = m0 + warp_m * 64 + mi * 16 + g;
            int col = n0 + warp_n * 64 + ni * 8 + tg * 2;
            *(float2*)&C[(size_t)row * outN + col] =
                make_float2(acc[mi][ni][0], acc[mi][ni][1]);
            *(float2*)&C[(size_t)(row + 8) * outN + col] =
                make_float2(acc[mi][ni][2], acc[mi][ni][3]);
        }
    }
}

// ---------------- RoPE + operand-format prepasses ----------------
__global__ void rope_q_prep(const float* __restrict__ qkv, const float* __restrict__ cs,
                            const float* __restrict__ sn,
                            uint32_t* __restrict__ qh, uint32_t* __restrict__ ql)
{
    const float scale = 0.08838834764831845f;
    int idx = blockIdx.x * blockDim.x + threadIdx.x;
    if (idx >= SEQ * NH * 64) return;
    int pr = idx & 63;
    int hh = (idx >> 6) & 31;
    int ss = idx >> 11;
    float c = cs[ss * 64 + pr], si = sn[ss * 64 + pr];
    float2 ri = *(const float2*)&qkv[(size_t)ss * QKVN + hh * HD + 2 * pr];
    float ox = (ri.x * c - ri.y * si) * scale;
    float oy = (ri.x * si + ri.y * c) * scale;
    float hx = bfhi(ox), hy = bfhi(oy);
    size_t w = ((size_t)hh * SEQ + ss) * 64 + pr;
    qh[w] = pack2bf(hx, hy);
    ql[w] = pack2bf(ox - hx, oy - hy);
}

__global__ void rope_k_prep(const float* __restrict__ qkv, const float* __restrict__ cs,
                            const float* __restrict__ sn,
                            uint32_t* __restrict__ kh, uint32_t* __restrict__ kl)
{
    int idx = blockIdx.x * blockDim.x + threadIdx.x;
    if (idx >= SEQ * NKV * 64) return;
    int pr = idx & 63;
    int hh = (idx >> 6) & 7;
    int ss = idx >> 9;
    float c = cs[ss * 64 + pr], si = sn[ss * 64 + pr];
    float2 ri = *(const float2*)&qkv[(size_t)ss * QKVN + DIM + hh * HD + 2 * pr];
    float ox = ri.x * c - ri.y * si;
    float oy = ri.x * si + ri.y * c;
    float hx = bfhi(ox), hy = bfhi(oy);
    size_t w = ((size_t)hh * SEQ + ss) * 64 + pr;
    kh[w] = pack2bf(hx, hy);
    kl[w] = pack2bf(ox - hx, oy - hy);
}

// V transpose: [s][c] -> [c][s], tf32-rounded
__global__ void v_prep(const float* __restrict__ qkv, float* __restrict__ vt)
{
    __shared__ float t[32][33];
    int s0 = blockIdx.x * 32, c0 = blockIdx.y * 32;
    int tx = threadIdx.x, ty = threadIdx.y;
#pragma unroll
    for (int j = 0; j < 32; j += 8)
        t[ty + j][tx] = qkv[(size_t)(s0 + ty + j) * QKVN + DIM + 1024 + c0 + tx];
    __syncthreads();
#pragma unroll
    for (int j = 0; j < 32; j += 8)
        vt[(size_t)(c0 + ty + j) * SEQ + s0 + tx] = tf32f(t[tx][ty + j]);
}

// ---------------- Tensor-core flash attention: cp.async pipelined (R6/R9) --------
#define AQH 0
#define AQL 8704
#define AKH 17408
#define AKL 26112
#define KSTG 4352
#define AVT 34816
#define APS 43520
#define ATT_WORDS 52224    // 208896 bytes

__global__ __launch_bounds__(256, 1) void attn_tc(const uint32_t* __restrict__ qh,
                                                  const uint32_t* __restrict__ ql,
                                                  const uint32_t* __restrict__ kh,
                                                  const uint32_t* __restrict__ kl,
                                                  const float* __restrict__ vt,
                                                  float* __restrict__ O)
{
    extern __shared__ float sm[];
    int tid = threadIdx.x, wid = tid >> 5, lane = tid & 31;
    int qt = (int)gridDim.x - 1 - (int)blockIdx.x;   // longest-first
    int h = blockIdx.y, kvh = h >> 2;
    int qm0 = qt * 128;
    int g = lane >> 2, tg = lane & 3;
    int wr0 = wid * 16;
    int row0 = qm0 + wr0 + g, row1 = row0 + 8;

    uint32_t shb = (uint32_t)__cvta_generic_to_shared(sm);

    // ---- prologue: issue Q tile + K tile 0 ----
    {
        const uint32_t* qsrc_h = qh + ((size_t)h * SEQ + qm0) * 64;
        const uint32_t* qsrc_l = ql + ((size_t)h * SEQ + qm0) * 64;
        for (int i = tid; i < 2048; i += 256) {
            int r = i >> 4, ch = (i & 15) * 4;
            asm volatile("cp.async.cg.shared.global [%0], [%1], 16;"
                         :: "r"(shb + ((AQH + r * 68 + ch) << 2)), "l"(qsrc_h + r * 64 + ch));
            asm volatile("cp.async.cg.shared.global [%0], [%1], 16;"
                         :: "r"(shb + ((AQL + r * 68 + ch) << 2)), "l"(qsrc_l + r * 64 + ch));
        }
        const uint32_t* ksrc_h = kh + (size_t)kvh * SEQ * 64;
        const uint32_t* ksrc_l = kl + (size_t)kvh * SEQ * 64;
        for (int i = tid; i < 1024; i += 256) {
            int r = i >> 4, ch = (i & 15) * 4;
            asm volatile("cp.async.cg.shared.global [%0], [%1], 16;"
                         :: "r"(shb + ((AKH + r * 68 + ch) << 2)), "l"(ksrc_h + r * 64 + ch));
            asm volatile("cp.async.cg.shared.global [%0], [%1], 16;"
                         :: "r"(shb + ((AKL + r * 68 + ch) << 2)), "l"(ksrc_l + r * 64 + ch));
        }
        asm volatile("cp.async.commit_group;");
    }

    int la = lane & 15, hiq = lane >> 4;
    uint32_t aQH = shb + (uint32_t)((AQH + (wr0 + la) * 68 + hiq * 4) << 2);
    uint32_t aQL = shb + (uint32_t)((AQL + (wr0 + la) * 68 + hiq * 4) << 2);
    uint32_t bKHb = shb + (uint32_t)((AKH + la * 68 + hiq * 4) << 2);
    uint32_t bKLb = shb + (uint32_t)((AKL + la * 68 + hiq * 4) << 2);
    uint32_t aP  = shb + (uint32_t)((APS + (wr0 + la) * 68 + hiq * 4) << 2);
    int rbv = (lane & 7) + ((lane >> 4) << 3), bhiv = (lane >> 3) & 1;
    uint32_t bV = shb + (uint32_t)((AVT + rbv * 68 + bhiv * 4) << 2);

    float oa[16][4];
#pragma unroll
    for (int i = 0; i < 16; i++)
#pragma unroll
        for (int j = 0; j < 4; j++) oa[i][j] = 0.0f;
    float m0 = -1e30f, m1 = -1e30f, l0 = 0.0f, l1 = 0.0f;

    int ktmax = 2 * qt + 1;
    const uint32_t* ksrc_h = kh + (size_t)kvh * SEQ * 64;
    const uint32_t* ksrc_l = kl + (size_t)kvh * SEQ * 64;
    const float*    vsrc   = vt + (size_t)kvh * HD * SEQ;

    for (int kt = 0; kt <= ktmax; kt++) {
        int kn0 = kt * 64;
        int st = kt & 1;
        uint32_t stoff = (uint32_t)(st * KSTG * 4);

        __syncthreads();   // V buffer + next K stage free

        for (int i = tid; i < 2048; i += 256) {
            int c = i >> 4, ch = (i & 15) * 4;
            asm volatile("cp.async.cg.shared.global [%0], [%1], 16;"
                         :: "r"(shb + ((AVT + c * 68 + ch) << 2)),
                            "l"(vsrc + (size_t)c * SEQ + kn0 + ch));
        }
        asm volatile("cp.async.commit_group;");

        if (kt < ktmax) {
            uint32_t nstoff = (uint32_t)((st ^ 1) * KSTG * 4);
            int kn1 = kn0 + 64;
            for (int i = tid; i < 1024; i += 256) {
                int r = i >> 4, ch = (i & 15) * 4;
                asm volatile("cp.async.cg.shared.global [%0], [%1], 16;"
                             :: "r"(shb + ((AKH + r * 68 + ch) << 2) + nstoff),
                                "l"(ksrc_h + (size_t)(kn1 + r) * 64 + ch));
                asm volatile("cp.async.cg.shared.global [%0], [%1], 16;"
                             :: "r"(shb + ((AKL + r * 68 + ch) << 2) + nstoff),
                                "l"(ksrc_l + (size_t)(kn1 + r) * 64 + ch));
            }
        }
        asm volatile("cp.async.commit_group;");

        asm volatile("cp.async.wait_group 2;");   // K(kt) (and Q) ready
        __syncthreads();

        bool skip = (qm0 + wr0 + 15 < kn0);
        float sc[8][4];

        if (!skip) {
            // ---- QK^T: bf16 hi/lo 3-term ----
#pragma unroll
            for (int i = 0; i < 8; i++)
#pragma unroll
                for (int j = 0; j < 4; j++) sc[i][j] = 0.0f;

#pragma unroll 2
            for (int ks = 0; ks < 8; ks++) {
                uint32_t ah[4], al[4];
                ldm4(ah, aQH + ks * 32);
                ldm4(al, aQL + ks * 32);
#pragma unroll
                for (int npp = 0; npp < 4; npp++) {
                    uint32_t bh[4], bl[4];
                    ldm4(bh, bKHb + stoff + (uint32_t)(npp * 16 * 68 * 4) + ks * 32);
                    ldm4(bl, bKLb + stoff + (uint32_t)(npp * 16 * 68 * 4) + ks * 32);
                    mma16(sc[2 * npp],     ah, bh[0], bh[2]);
                    mma16(sc[2 * npp],     al, bh[0], bh[2]);
                    mma16(sc[2 * npp],     ah, bl[0], bl[2]);
                    mma16(sc[2 * npp + 1], ah, bh[1], bh[3]);
                    mma16(sc[2 * npp + 1], al, bh[1], bh[3]);
                    mma16(sc[2 * npp + 1], ah, bl[1], bl[3]);
                }
            }

            if (kt >= 2 * qt) {
#pragma unroll
                for (int nf = 0; nf < 8; nf++) {
                    int kc = kn0 + nf * 8 + 2 * tg;
                    if (kc > row0)     sc[nf][0] = -1e30f;
                    if (kc + 1 > row0) sc[nf][1] = -1e30f;
                    if (kc > row1)     sc[nf][2] = -1e30f;
                    if (kc + 1 > row1) sc[nf][3] = -1e30f;
                }
            }

            float rm0 = -1e30f, rm1 = -1e30f;
#pragma unroll
            for (int nf = 0; nf < 8; nf++) {
                rm0 = fmaxf(rm0, fmaxf(sc[nf][0], sc[nf][1]));
                rm1 = fmaxf(rm1, fmaxf(sc[nf][2], sc[nf][3]));
            }
            rm0 = fmaxf(rm0, __shfl_xor_sync(0xffffffffu, rm0, 1));
            rm0 = fmaxf(rm0, __shfl_xor_sync(0xffffffffu, rm0, 2));
            rm1 = fmaxf(rm1, __shfl_xor_sync(0xffffffffu, rm1, 1));
            rm1 = fmaxf(rm1, __shfl_xor_sync(0xffffffffu, rm1, 2));
            float mn0 = fmaxf(m0, rm0), mn1 = fmaxf(m1, rm1);
            float fac0 = __expf(m0 - mn0), fac1 = __expf(m1 - mn1);
            float rs0 = 0.0f, rs1 = 0.0f;
#pragma unroll
            for (int nf = 0; nf < 8; nf++) {
                sc[nf][0] = __expf(sc[nf][0] - mn0);
                sc[nf][1] = __expf(sc[nf][1] - mn0);
                sc[nf][2] = __expf(sc[nf][2] - mn1);
                sc[nf][3] = __expf(sc[nf][3] - mn1);
                rs0 += sc[nf][0] + sc[nf][1];
                rs1 += sc[nf][2] + sc[nf][3];
            }
            rs0 += __shfl_xor_sync(0xffffffffu, rs0, 1);
            rs0 += __shfl_xor_sync(0xffffffffu, rs0, 2);
            rs1 += __shfl_xor_sync(0xffffffffu, rs1, 1);
            rs1 += __shfl_xor_sync(0xffffffffu, rs1, 2);
            l0 = l0 * fac0 + rs0; m0 = mn0;
            l1 = l1 * fac1 + rs1; m1 = mn1;
#pragma unroll
            for (int nf = 0; nf < 16; nf++) {
                oa[nf][0] *= fac0; oa[nf][1] *= fac0;
                oa[nf][2] *= fac1; oa[nf][3] *= fac1;
            }
        }

        asm volatile("cp.async.wait_group 1;");   // V(kt) ready
        __syncthreads();

        if (!skip) {
#pragma unroll
            for (int nf = 0; nf < 8; nf++) {
                *(float2*)&sm[APS + (wr0 + g) * 68 + nf * 8 + 2 * tg] =
                    make_float2(tf32f(sc[nf][0]), tf32f(sc[nf][1]));
                *(float2*)&sm[APS + (wr0 + g + 8) * 68 + nf * 8 + 2 * tg] =
                    make_float2(tf32f(sc[nf][2]), tf32f(sc[nf][3]));
            }
            __syncwarp();

#pragma unroll 2
            for (int ks2 = 0; ks2 < 8; ks2++) {
                uint32_t pa[4];
                ldm4(pa, aP + ks2 * 32);
#pragma unroll
                for (int np = 0; np < 8; np++) {
                    uint32_t bv[4];
                    ldm4(bv, bV + (uint32_t)(np * 16 * 68 * 4) + ks2 * 32);
                    mma8(oa[2 * np],     pa, bv[0], bv[1]);
                    mma8(oa[2 * np + 1], pa, bv[2], bv[3]);
                }
            }
        }
    }

    // epilogue: rna-rounded att (O-proj A operand is pre-rounded)
    float inv0 = 1.0f / l0, inv1 = 1.0f / l1;
#pragma unroll
    for (int nf = 0; nf < 16; nf++) {
        int col = nf * 8 + 2 * tg;
        *(float2*)&O[((size_t)row0 * NH + h) * HD + col] =
            make_float2(tf32f(oa[nf][0] * inv0), tf32f(oa[nf][1] * inv0));
        *(float2*)&O[((size_t)row1 * NH + h) * HD + col] =
            make_float2(tf32f(oa[nf][2] * inv1), tf32f(oa[nf][3] * inv1));
    }
}

// ---------------- launch ----------------
extern "C" void kernel_launch(void* const* d_in, const int* in_sizes, int n_in,
                              void* d_out, int out_size)
{
    const float* x  = (const float*)d_in[0];
    const float* wq = (const float*)d_in[1];
    const float* wk = (const float*)d_in[2];
    const float* wv = (const float*)d_in[3];
    const float* wo = (const float*)d_in[4];
    const float* fc = (const float*)d_in[5];
    const float* fs = (const float*)d_in[6];
    float* out = (float*)d_out;

    float *qkv, *att, *vtb, *xc, *wqc, *wkc, *wvc, *woc;
    uint32_t *qhb, *qlb, *khb, *klb;
    cudaGetSymbolAddress((void**)&qkv, g_qkv);
    cudaGetSymbolAddress((void**)&att, g_att);
    cudaGetSymbolAddress((void**)&xc,  g_xc);
    cudaGetSymbolAddress((void**)&wqc, g_wqc);
    cudaGetSymbolAddress((void**)&wkc, g_wkc);
    cudaGetSymbolAddress((void**)&wvc, g_wvc);
    cudaGetSymbolAddress((void**)&woc, g_woc);
    cudaGetSymbolAddress((void**)&qhb, g_qh);
    cudaGetSymbolAddress((void**)&qlb, g_ql);
    cudaGetSymbolAddress((void**)&khb, g_kh);
    cudaGetSymbolAddress((void**)&klb, g_kl);
    cudaGetSymbolAddress((void**)&vtb, g_vt);

    int t = 256;
    cvt_rna<<<(SEQ * DIM / 4 + t - 1) / t, t>>>(x, xc, SEQ * DIM / 4);
    cvt_rna<<<(DIM * DIM / 4 + t - 1) / t, t>>>(wq, wqc, DIM * DIM / 4);
    cvt_rna<<<(1024 * DIM / 4 + t - 1) / t, t>>>(wk, wkc, 1024 * DIM / 4);
    cvt_rna<<<(1024 * DIM / 4 + t - 1) / t, t>>>(wv, wvc, 1024 * DIM / 4);
    cvt_rna<<<(DIM * DIM / 4 + t - 1) / t, t>>>(wo, woc, DIM * DIM / 4);

    cudaFuncSetAttribute(gemm_tf32, cudaFuncAttributeMaxDynamicSharedMemorySize, GSMEM_BYTES);

    dim3 blk(256);
    gemm_tf32<<<dim3(QKVN / 256, SEQ / 128), blk, GSMEM_BYTES>>>(xc, wqc, wkc, wvc, qkv, SEQ, QKVN, DIM);

    rope_q_prep<<<(SEQ * NH * 64 + 255) / 256, 256>>>(qkv, fc, fs, qhb, qlb);
    rope_k_prep<<<(SEQ * NKV * 64 + 255) / 256, 256>>>(qkv, fc, fs, khb, klb);
    v_prep<<<dim3(SEQ / 32, 1024 / 32), dim3(32, 8)>>>(qkv, vtb);

    int ash = ATT_WORDS * (int)sizeof(float);
    cudaFuncSetAttribute(attn_tc, cudaFuncAttributeMaxDynamicSharedMemorySize, ash);
    attn_tc<<<dim3(SEQ / 128, NH), blk, ash>>>(qhb, qlb, khb, klb, vtb, att);

    gemm_tf32<<<dim3(DIM / 256, SEQ / 128), blk, GSMEM_BYTES>>>(att, woc, woc, woc, out, SEQ, DIM, DIM);
}

// round 12
// speedup vs baseline: 1.0493x; 1.0493x over previous
#include <cuda_runtime.h>
#include <cuda_bf16.h>
#include <cstdint>

#define SEQ 2048
#define DIM 4096
#define NH  32
#define NKV 8
#define HD  128
#define QKVN 6144   // fused projection N (4096 q + 1024 k + 1024 v)

// ---------------- scratch (device globals: no allocation allowed) ----------------
__device__ float    g_qkv[(size_t)SEQ * QKVN];       // fused q|k|v (fp32)
__device__ float    g_att[(size_t)SEQ * DIM];        // attention out (rna-rounded)
__device__ float    g_xc[(size_t)SEQ * DIM];         // rna-rounded x
__device__ float    g_wqc[(size_t)DIM * DIM];        // rna-rounded wq
__device__ float    g_wkc[(size_t)1024 * DIM];       // rna-rounded wk
__device__ float    g_wvc[(size_t)1024 * DIM];       // rna-rounded wv
__device__ float    g_woc[(size_t)DIM * DIM];        // rna-rounded wo
__device__ uint32_t g_qh[(size_t)NH  * SEQ * 64];    // Q hi  bf16x2 (scaled, roped)
__device__ uint32_t g_ql[(size_t)NH  * SEQ * 64];    // Q lo  bf16x2
__device__ uint32_t g_kh[(size_t)NKV * SEQ * 64];    // K hi  bf16x2 (roped)
__device__ uint32_t g_kl[(size_t)NKV * SEQ * 64];    // K lo  bf16x2
__device__ float    g_vt[(size_t)NKV * HD * SEQ];    // V transposed [c][s], tf32

__device__ __forceinline__ uint32_t cvt_tf32(float x) {
    uint32_t r;
    asm("cvt.rna.tf32.f32 %0, %1;" : "=r"(r) : "f"(x));
    return r;
}
__device__ __forceinline__ float tf32f(float x) { return __uint_as_float(cvt_tf32(x)); }
__device__ __forceinline__ void ldm4(uint32_t* r, uint32_t addr) {
    asm volatile("ldmatrix.sync.aligned.m8n8.x4.shared.b16 {%0,%1,%2,%3}, [%4];"
                 : "=r"(r[0]), "=r"(r[1]), "=r"(r[2]), "=r"(r[3]) : "r"(addr));
}
__device__ __forceinline__ void ldm2(uint32_t* r, uint32_t addr) {
    asm volatile("ldmatrix.sync.aligned.m8n8.x2.shared.b16 {%0,%1}, [%2];"
                 : "=r"(r[0]), "=r"(r[1]) : "r"(addr));
}
__device__ __forceinline__ void mma8(float* c, const uint32_t* a, uint32_t b0, uint32_t b1) {
    asm volatile("mma.sync.aligned.m16n8k8.row.col.f32.tf32.tf32.f32 "
                 "{%0,%1,%2,%3}, {%4,%5,%6,%7}, {%8,%9}, {%0,%1,%2,%3};"
                 : "+f"(c[0]), "+f"(c[1]), "+f"(c[2]), "+f"(c[3])
                 : "r"(a[0]), "r"(a[1]), "r"(a[2]), "r"(a[3]), "r"(b0), "r"(b1));
}
__device__ __forceinline__ void mma16(float* c, const uint32_t* a, uint32_t b0, uint32_t b1) {
    asm volatile("mma.sync.aligned.m16n8k16.row.col.f32.bf16.bf16.f32 "
                 "{%0,%1,%2,%3}, {%4,%5,%6,%7}, {%8,%9}, {%0,%1,%2,%3};"
                 : "+f"(c[0]), "+f"(c[1]), "+f"(c[2]), "+f"(c[3])
                 : "r"(a[0]), "r"(a[1]), "r"(a[2]), "r"(a[3]), "r"(b0), "r"(b1));
}
__device__ __forceinline__ uint32_t pack2bf(float a, float b) {
    __nv_bfloat162 t = __floats2bfloat162_rn(a, b);
    return *(uint32_t*)&t;
}
__device__ __forceinline__ float bfhi(float a) {
    return __bfloat162float(__float2bfloat16(a));
}

// ---------------- prepass: rna-round fp32 to tf32 values ----------------
__global__ void cvt_rna(const float* __restrict__ in, float* __restrict__ out, int n4)
{
    int i = blockIdx.x * blockDim.x + threadIdx.x;
    if (i >= n4) return;
    float4 v = ((const float4*)in)[i];
    v.x = tf32f(v.x); v.y = tf32f(v.y); v.z = tf32f(v.z); v.w = tf32f(v.w);
    ((float4*)out)[i] = v;
}

// ---------------- TF32 NT GEMM: 128x128 block, 2 CTAs/SM ------------------------
// 256 threads (8 warps 2x4), warp tile 64x32, BK=32, register-staged double buffer.
// Inputs pre-rounded (rna). Occupancy 2 hides barrier/ldmatrix stalls.
#define SA 36
#define BUFE (2 * 128 * SA)             // words per stage (A tile + B tile)
#define GSMEM_BYTES (2 * BUFE * 4)      // 73728

__global__ __launch_bounds__(256, 2) void gemm_tf32(const float* __restrict__ A,
                                                    const float* __restrict__ B0,
                                                    const float* __restrict__ B1,
                                                    const float* __restrict__ B2,
                                                    float* __restrict__ C,
                                                    int M, int outN, int K)
{
    extern __shared__ float sh[];
    int tid = threadIdx.x;
    int wid = tid >> 5, lane = tid & 31;
    int warp_m = wid >> 2, warp_n = wid & 3;
    int m0 = blockIdx.y * 128, n0 = blockIdx.x * 128;

    const float* Bsel;
    int nloc;
    if (n0 < DIM)                { Bsel = B0; nloc = n0; }
    else if (n0 < DIM + 1024)    { Bsel = B1; nloc = n0 - DIM; }
    else                         { Bsel = B2; nloc = n0 - DIM - 1024; }

    int lr = tid >> 3;          // 0..31
    int lc = (tid & 7) * 4;     // 0..28
    const float* Aq = A + (size_t)(m0 + lr) * K + lc;
    const float* Bq = Bsel + (size_t)(nloc + lr) * K + lc;

    float4 ra[4], rb[4];
    uint32_t shbase = (uint32_t)__cvta_generic_to_shared(sh);

    int la = lane & 15, ahi = lane >> 4;
    int lb = lane & 7, bhi = (lane >> 3) & 1;
    uint32_t a_addr[4], b_addr[4];
#pragma unroll
    for (int mi = 0; mi < 4; mi++)
        a_addr[mi] = shbase + (uint32_t)(((warp_m * 64 + mi * 16 + la) * SA + ahi * 4) << 2);
#pragma unroll
    for (int ni = 0; ni < 4; ni++)
        b_addr[ni] = shbase + (uint32_t)((128 * SA + (warp_n * 32 + ni * 8 + lb) * SA + bhi * 4) << 2);

    float acc[4][4][4];
#pragma unroll
    for (int mi = 0; mi < 4; mi++)
#pragma unroll
        for (int ni = 0; ni < 4; ni++)
#pragma unroll
            for (int t = 0; t < 4; t++) acc[mi][ni][t] = 0.0f;

    const int iters = K >> 5;

    auto store_stage = [&](int s) {
        float* As = sh + s * BUFE;
        float* Bs = As + 128 * SA;
#pragma unroll
        for (int rr = 0; rr < 4; rr++) {
            *(float4*)&As[(lr + 32 * rr) * SA + lc] = ra[rr];
            *(float4*)&Bs[(lr + 32 * rr) * SA + lc] = rb[rr];
        }
    };

    // prologue: tile 0
#pragma unroll
    for (int rr = 0; rr < 4; rr++) {
        ra[rr] = *(const float4*)(Aq + (size_t)rr * 32 * K);
        rb[rr] = *(const float4*)(Bq + (size_t)rr * 32 * K);
    }
    store_stage(0);
    __syncthreads();

    for (int it = 0; it < iters; ++it) {
        int cur = it & 1;
        if (it + 1 < iters) {
            int ko = (it + 1) << 5;
#pragma unroll
            for (int rr = 0; rr < 4; rr++) {
                ra[rr] = *(const float4*)(Aq + (size_t)rr * 32 * K + ko);
                rb[rr] = *(const float4*)(Bq + (size_t)rr * 32 * K + ko);
            }
        }

        uint32_t boff = (uint32_t)(cur * BUFE * 4);
#pragma unroll
        for (int ks = 0; ks < 4; ks++) {
            uint32_t af[4][4], bf2[4][2];
#pragma unroll
            for (int mi = 0; mi < 4; mi++) ldm4(af[mi], a_addr[mi] + boff + ks * 32);
#pragma unroll
            for (int ni = 0; ni < 4; ni++) ldm2(bf2[ni], b_addr[ni] + boff + ks * 32);
#pragma unroll
            for (int mi = 0; mi < 4; mi++)
#pragma unroll
                for (int ni = 0; ni < 4; ni++)
                    mma8(acc[mi][ni], af[mi], bf2[ni][0], bf2[ni][1]);
        }

        if (it + 1 < iters) {
            store_stage(cur ^ 1);
            __syncthreads();
        }
    }

    int g = lane >> 2, tg = lane & 3;
#pragma unroll
    for (int mi = 0; mi < 4; mi++) {
#pragma unroll
        for (int ni = 0; ni < 4; ni++) {
            int row = m0 + warp_m * 64 + mi * 16 + g;
            int col = n0 + warp_n * 32 + ni * 8 + tg * 2;
            *(float2*)&C[(size_t)row * outN + col] =
                make_float2(acc[mi][ni][0], acc[mi][ni][1]);
            *(float2*)&C[(size_t)(row + 8) * outN + col] =
                make_float2(acc[mi][ni][2], acc[mi][ni][3]);
        }
    }
}

// ---------------- RoPE + operand-format prepasses ----------------
__global__ void rope_q_prep(const float* __restrict__ qkv, const float* __restrict__ cs,
                            const float* __restrict__ sn,
                            uint32_t* __restrict__ qh, uint32_t* __restrict__ ql)
{
    const float scale = 0.08838834764831845f;
    int idx = blockIdx.x * blockDim.x + threadIdx.x;
    if (idx >= SEQ * NH * 64) return;
    int pr = idx & 63;
    int hh = (idx >> 6) & 31;
    int ss = idx >> 11;
    float c = cs[ss * 64 + pr], si = sn[ss * 64 + pr];
    float2 ri = *(const float2*)&qkv[(size_t)ss * QKVN + hh * HD + 2 * pr];
    float ox = (ri.x * c - ri.y * si) * scale;
    float oy = (ri.x * si + ri.y * c) * scale;
    float hx = bfhi(ox), hy = bfhi(oy);
    size_t w = ((size_t)hh * SEQ + ss) * 64 + pr;
    qh[w] = pack2bf(hx, hy);
    ql[w] = pack2bf(ox - hx, oy - hy);
}

__global__ void rope_k_prep(const float* __restrict__ qkv, const float* __restrict__ cs,
                            const float* __restrict__ sn,
                            uint32_t* __restrict__ kh, uint32_t* __restrict__ kl)
{
    int idx = blockIdx.x * blockDim.x + threadIdx.x;
    if (idx >= SEQ * NKV * 64) return;
    int pr = idx & 63;
    int hh = (idx >> 6) & 7;
    int ss = idx >> 9;
    float c = cs[ss * 64 + pr], si = sn[ss * 64 + pr];
    float2 ri = *(const float2*)&qkv[(size_t)ss * QKVN + DIM + hh * HD + 2 * pr];
    float ox = ri.x * c - ri.y * si;
    float oy = ri.x * si + ri.y * c;
    float hx = bfhi(ox), hy = bfhi(oy);
    size_t w = ((size_t)hh * SEQ + ss) * 64 + pr;
    kh[w] = pack2bf(hx, hy);
    kl[w] = pack2bf(ox - hx, oy - hy);
}

// V transpose: [s][c] -> [c][s], tf32-rounded
__global__ void v_prep(const float* __restrict__ qkv, float* __restrict__ vt)
{
    __shared__ float t[32][33];
    int s0 = blockIdx.x * 32, c0 = blockIdx.y * 32;
    int tx = threadIdx.x, ty = threadIdx.y;
#pragma unroll
    for (int j = 0; j < 32; j += 8)
        t[ty + j][tx] = qkv[(size_t)(s0 + ty + j) * QKVN + DIM + 1024 + c0 + tx];
    __syncthreads();
#pragma unroll
    for (int j = 0; j < 32; j += 8)
        vt[(size_t)(c0 + ty + j) * SEQ + s0 + tx] = tf32f(t[tx][ty + j]);
}

// ---------------- Tensor-core flash attention: cp.async pipelined (R6/R9) --------
#define AQH 0
#define AQL 8704
#define AKH 17408
#define AKL 26112
#define KSTG 4352
#define AVT 34816
#define APS 43520
#define ATT_WORDS 52224    // 208896 bytes

__global__ __launch_bounds__(256, 1) void attn_tc(const uint32_t* __restrict__ qh,
                                                  const uint32_t* __restrict__ ql,
                                                  const uint32_t* __restrict__ kh,
                                                  const uint32_t* __restrict__ kl,
                                                  const float* __restrict__ vt,
                                                  float* __restrict__ O)
{
    extern __shared__ float sm[];
    int tid = threadIdx.x, wid = tid >> 5, lane = tid & 31;
    int qt = (int)gridDim.x - 1 - (int)blockIdx.x;   // longest-first
    int h = blockIdx.y, kvh = h >> 2;
    int qm0 = qt * 128;
    int g = lane >> 2, tg = lane & 3;
    int wr0 = wid * 16;
    int row0 = qm0 + wr0 + g, row1 = row0 + 8;

    uint32_t shb = (uint32_t)__cvta_generic_to_shared(sm);

    // ---- prologue: issue Q tile + K tile 0 ----
    {
        const uint32_t* qsrc_h = qh + ((size_t)h * SEQ + qm0) * 64;
        const uint32_t* qsrc_l = ql + ((size_t)h * SEQ + qm0) * 64;
        for (int i = tid; i < 2048; i += 256) {
            int r = i >> 4, ch = (i & 15) * 4;
            asm volatile("cp.async.cg.shared.global [%0], [%1], 16;"
                         :: "r"(shb + ((AQH + r * 68 + ch) << 2)), "l"(qsrc_h + r * 64 + ch));
            asm volatile("cp.async.cg.shared.global [%0], [%1], 16;"
                         :: "r"(shb + ((AQL + r * 68 + ch) << 2)), "l"(qsrc_l + r * 64 + ch));
        }
        const uint32_t* ksrc_h = kh + (size_t)kvh * SEQ * 64;
        const uint32_t* ksrc_l = kl + (size_t)kvh * SEQ * 64;
        for (int i = tid; i < 1024; i += 256) {
            int r = i >> 4, ch = (i & 15) * 4;
            asm volatile("cp.async.cg.shared.global [%0], [%1], 16;"
                         :: "r"(shb + ((AKH + r * 68 + ch) << 2)), "l"(ksrc_h + r * 64 + ch));
            asm volatile("cp.async.cg.shared.global [%0], [%1], 16;"
                         :: "r"(shb + ((AKL + r * 68 + ch) << 2)), "l"(ksrc_l + r * 64 + ch));
        }
        asm volatile("cp.async.commit_group;");
    }

    int la = lane & 15, hiq = lane >> 4;
    uint32_t aQH = shb + (uint32_t)((AQH + (wr0 + la) * 68 + hiq * 4) << 2);
    uint32_t aQL = shb + (uint32_t)((AQL + (wr0 + la) * 68 + hiq * 4) << 2);
    uint32_t bKHb = shb + (uint32_t)((AKH + la * 68 + hiq * 4) << 2);
    uint32_t bKLb = shb + (uint32_t)((AKL + la * 68 + hiq * 4) << 2);
    uint32_t aP  = shb + (uint32_t)((APS + (wr0 + la) * 68 + hiq * 4) << 2);
    int rbv = (lane & 7) + ((lane >> 4) << 3), bhiv = (lane >> 3) & 1;
    uint32_t bV = shb + (uint32_t)((AVT + rbv * 68 + bhiv * 4) << 2);

    float oa[16][4];
#pragma unroll
    for (int i = 0; i < 16; i++)
#pragma unroll
        for (int j = 0; j < 4; j++) oa[i][j] = 0.0f;
    float m0 = -1e30f, m1 = -1e30f, l0 = 0.0f, l1 = 0.0f;

    int ktmax = 2 * qt + 1;
    const uint32_t* ksrc_h = kh + (size_t)kvh * SEQ * 64;
    const uint32_t* ksrc_l = kl + (size_t)kvh * SEQ * 64;
    const float*    vsrc   = vt + (size_t)kvh * HD * SEQ;

    for (int kt = 0; kt <= ktmax; kt++) {
        int kn0 = kt * 64;
        int st = kt & 1;
        uint32_t stoff = (uint32_t)(st * KSTG * 4);

        __syncthreads();   // V buffer + next K stage free

        for (int i = tid; i < 2048; i += 256) {
            int c = i >> 4, ch = (i & 15) * 4;
            asm volatile("cp.async.cg.shared.global [%0], [%1], 16;"
                         :: "r"(shb + ((AVT + c * 68 + ch) << 2)),
                            "l"(vsrc + (size_t)c * SEQ + kn0 + ch));
        }
        asm volatile("cp.async.commit_group;");

        if (kt < ktmax) {
            uint32_t nstoff = (uint32_t)((st ^ 1) * KSTG * 4);
            int kn1 = kn0 + 64;
            for (int i = tid; i < 1024; i += 256) {
                int r = i >> 4, ch = (i & 15) * 4;
                asm volatile("cp.async.cg.shared.global [%0], [%1], 16;"
                             :: "r"(shb + ((AKH + r * 68 + ch) << 2) + nstoff),
                                "l"(ksrc_h + (size_t)(kn1 + r) * 64 + ch));
                asm volatile("cp.async.cg.shared.global [%0], [%1], 16;"
                             :: "r"(shb + ((AKL + r * 68 + ch) << 2) + nstoff),
                                "l"(ksrc_l + (size_t)(kn1 + r) * 64 + ch));
            }
        }
        asm volatile("cp.async.commit_group;");

        asm volatile("cp.async.wait_group 2;");   // K(kt) (and Q) ready
        __syncthreads();

        bool skip = (qm0 + wr0 + 15 < kn0);
        float sc[8][4];

        if (!skip) {
            // ---- QK^T: bf16 hi/lo 3-term ----
#pragma unroll
            for (int i = 0; i < 8; i++)
#pragma unroll
                for (int j = 0; j < 4; j++) sc[i][j] = 0.0f;

#pragma unroll 2
            for (int ks = 0; ks < 8; ks++) {
                uint32_t ah[4], al[4];
                ldm4(ah, aQH + ks * 32);
                ldm4(al, aQL + ks * 32);
#pragma unroll
                for (int npp = 0; npp < 4; npp++) {
                    uint32_t bh[4], bl[4];
                    ldm4(bh, bKHb + stoff + (uint32_t)(npp * 16 * 68 * 4) + ks * 32);
                    ldm4(bl, bKLb + stoff + (uint32_t)(npp * 16 * 68 * 4) + ks * 32);
                    mma16(sc[2 * npp],     ah, bh[0], bh[2]);
                    mma16(sc[2 * npp],     al, bh[0], bh[2]);
                    mma16(sc[2 * npp],     ah, bl[0], bl[2]);
                    mma16(sc[2 * npp + 1], ah, bh[1], bh[3]);
                    mma16(sc[2 * npp + 1], al, bh[1], bh[3]);
                    mma16(sc[2 * npp + 1], ah, bl[1], bl[3]);
                }
            }

            if (kt >= 2 * qt) {
#pragma unroll
                for (int nf = 0; nf < 8; nf++) {
                    int kc = kn0 + nf * 8 + 2 * tg;
                    if (kc > row0)     sc[nf][0] = -1e30f;
                    if (kc + 1 > row0) sc[nf][1] = -1e30f;
                    if (kc > row1)     sc[nf][2] = -1e30f;
                    if (kc + 1 > row1) sc[nf][3] = -1e30f;
                }
            }

            float rm0 = -1e30f, rm1 = -1e30f;
#pragma unroll
            for (int nf = 0; nf < 8; nf++) {
                rm0 = fmaxf(rm0, fmaxf(sc[nf][0], sc[nf][1]));
                rm1 = fmaxf(rm1, fmaxf(sc[nf][2], sc[nf][3]));
            }
            rm0 = fmaxf(rm0, __shfl_xor_sync(0xffffffffu, rm0, 1));
            rm0 = fmaxf(rm0, __shfl_xor_sync(0xffffffffu, rm0, 2));
            rm1 = fmaxf(rm1, __shfl_xor_sync(0xffffffffu, rm1, 1));
            rm1 = fmaxf(rm1, __shfl_xor_sync(0xffffffffu, rm1, 2));
            float mn0 = fmaxf(m0, rm0), mn1 = fmaxf(m1, rm1);
            float fac0 = __expf(m0 - mn0), fac1 = __expf(m1 - mn1);
            float rs0 = 0.0f, rs1 = 0.0f;
#pragma unroll
            for (int nf = 0; nf < 8; nf++) {
                sc[nf][0] = __expf(sc[nf][0] - mn0);
                sc[nf][1] = __expf(sc[nf][1] - mn0);
                sc[nf][2] = __expf(sc[nf][2] - mn1);
                sc[nf][3] = __expf(sc[nf][3] - mn1);
                rs0 += sc[nf][0] + sc[nf][1];
                rs1 += sc[nf][2] + sc[nf][3];
            }
            rs0 += __shfl_xor_sync(0xffffffffu, rs0, 1);
            rs0 += __shfl_xor_sync(0xffffffffu, rs0, 2);
            rs1 += __shfl_xor_sync(0xffffffffu, rs1, 1);
            rs1 += __shfl_xor_sync(0xffffffffu, rs1, 2);
            l0 = l0 * fac0 + rs0; m0 = mn0;
            l1 = l1 * fac1 + rs1; m1 = mn1;
#pragma unroll
            for (int nf = 0; nf < 16; nf++) {
                oa[nf][0] *= fac0; oa[nf][1] *= fac0;
                oa[nf][2] *= fac1; oa[nf][3] *= fac1;
            }
        }

        asm volatile("cp.async.wait_group 1;");   // V(kt) ready
        __syncthreads();

        if (!skip) {
#pragma unroll
            for (int nf = 0; nf < 8; nf++) {
                *(float2*)&sm[APS + (wr0 + g) * 68 + nf * 8 + 2 * tg] =
                    make_float2(tf32f(sc[nf][0]), tf32f(sc[nf][1]));
                *(float2*)&sm[APS + (wr0 + g + 8) * 68 + nf * 8 + 2 * tg] =
                    make_float2(tf32f(sc[nf][2]), tf32f(sc[nf][3]));
            }
            __syncwarp();

#pragma unroll 2
            for (int ks2 = 0; ks2 < 8; ks2++) {
                uint32_t pa[4];
                ldm4(pa, aP + ks2 * 32);
#pragma unroll
                for (int np = 0; np < 8; np++) {
                    uint32_t bv[4];
                    ldm4(bv, bV + (uint32_t)(np * 16 * 68 * 4) + ks2 * 32);
                    mma8(oa[2 * np],     pa, bv[0], bv[1]);
                    mma8(oa[2 * np + 1], pa, bv[2], bv[3]);
                }
            }
        }
    }

    // epilogue: rna-rounded att (O-proj A operand is pre-rounded)
    float inv0 = 1.0f / l0, inv1 = 1.0f / l1;
#pragma unroll
    for (int nf = 0; nf < 16; nf++) {
        int col = nf * 8 + 2 * tg;
        *(float2*)&O[((size_t)row0 * NH + h) * HD + col] =
            make_float2(tf32f(oa[nf][0] * inv0), tf32f(oa[nf][1] * inv0));
        *(float2*)&O[((size_t)row1 * NH + h) * HD + col] =
            make_float2(tf32f(oa[nf][2] * inv1), tf32f(oa[nf][3] * inv1));
    }
}

// ---------------- launch ----------------
extern "C" void kernel_launch(void* const* d_in, const int* in_sizes, int n_in,
                              void* d_out, int out_size)
{
    const float* x  = (const float*)d_in[0];
    const float* wq = (const float*)d_in[1];
    const float* wk = (const float*)d_in[2];
    const float* wv = (const float*)d_in[3];
    const float* wo = (const float*)d_in[4];
    const float* fc = (const float*)d_in[5];
    const float* fs = (const float*)d_in[6];
    float* out = (float*)d_out;

    float *qkv, *att, *vtb, *xc, *wqc, *wkc, *wvc, *woc;
    uint32_t *qhb, *qlb, *khb, *klb;
    cudaGetSymbolAddress((void**)&qkv, g_qkv);
    cudaGetSymbolAddress((void**)&att, g_att);
    cudaGetSymbolAddress((void**)&xc,  g_xc);
    cudaGetSymbolAddress((void**)&wqc, g_wqc);
    cudaGetSymbolAddress((void**)&wkc, g_wkc);
    cudaGetSymbolAddress((void**)&wvc, g_wvc);
    cudaGetSymbolAddress((void**)&woc, g_woc);
    cudaGetSymbolAddress((void**)&qhb, g_qh);
    cudaGetSymbolAddress((void**)&qlb, g_ql);
    cudaGetSymbolAddress((void**)&khb, g_kh);
    cudaGetSymbolAddress((void**)&klb, g_kl);
    cudaGetSymbolAddress((void**)&vtb, g_vt);

    int t = 256;
    cvt_rna<<<(SEQ * DIM / 4 + t - 1) / t, t>>>(x, xc, SEQ * DIM / 4);
    cvt_rna<<<(DIM * DIM / 4 + t - 1) / t, t>>>(wq, wqc, DIM * DIM / 4);
    cvt_rna<<<(1024 * DIM / 4 + t - 1) / t, t>>>(wk, wkc, 1024 * DIM / 4);
    cvt_rna<<<(1024 * DIM / 4 + t - 1) / t, t>>>(wv, wvc, 1024 * DIM / 4);
    cvt_rna<<<(DIM * DIM / 4 + t - 1) / t, t>>>(wo, woc, DIM * DIM / 4);

    cudaFuncSetAttribute(gemm_tf32, cudaFuncAttributeMaxDynamicSharedMemorySize, GSMEM_BYTES);

    dim3 blk(256);
    gemm_tf32<<<dim3(QKVN / 128, SEQ / 128), blk, GSMEM_BYTES>>>(xc, wqc, wkc, wvc, qkv, SEQ, QKVN, DIM);

    rope_q_prep<<<(SEQ * NH * 64 + 255) / 256, 256>>>(qkv, fc, fs, qhb, qlb);
    rope_k_prep<<<(SEQ * NKV * 64 + 255) / 256, 256>>>(qkv, fc, fs, khb, klb);
    v_prep<<<dim3(SEQ / 32, 1024 / 32), dim3(32, 8)>>>(qkv, vtb);

    int ash = ATT_WORDS * (int)sizeof(float);
    cudaFuncSetAttribute(attn_tc, cudaFuncAttributeMaxDynamicSharedMemorySize, ash);
    attn_tc<<<dim3(SEQ / 128, NH), blk, ash>>>(qhb, qlb, khb, klb, vtb, att);

    gemm_tf32<<<dim3(DIM / 128, SEQ / 128), blk, GSMEM_BYTES>>>(att, woc, woc, woc, out, SEQ, DIM, DIM);
}

// round 13
// speedup vs baseline: 1.0665x; 1.0164x over previous
#include <cuda_runtime.h>
#include <cuda_bf16.h>
#include <cstdint>

#define SEQ 2048
#define DIM 4096
#define NH  32
#define NKV 8
#define HD  128
#define QKVN 6144   // fused projection N (4096 q + 1024 k + 1024 v)

// ---------------- scratch (device globals: no allocation allowed) ----------------
__device__ float    g_qkv[(size_t)SEQ * QKVN];       // fused q|k|v (fp32)
__device__ float    g_att[(size_t)SEQ * DIM];        // attention out (rna-rounded)
__device__ float    g_xc[(size_t)SEQ * DIM];         // rna-rounded x
__device__ float    g_wqc[(size_t)DIM * DIM];        // rna-rounded wq
__device__ float    g_wkc[(size_t)1024 * DIM];       // rna-rounded wk
__device__ float    g_wvc[(size_t)1024 * DIM];       // rna-rounded wv
__device__ float    g_woc[(size_t)DIM * DIM];        // rna-rounded wo
__device__ uint32_t g_qh[(size_t)NH  * SEQ * 64];    // Q hi  bf16x2 (scaled, roped)
__device__ uint32_t g_ql[(size_t)NH  * SEQ * 64];    // Q lo  bf16x2
__device__ uint32_t g_kh[(size_t)NKV * SEQ * 64];    // K hi  bf16x2 (roped)
__device__ uint32_t g_kl[(size_t)NKV * SEQ * 64];    // K lo  bf16x2
__device__ float    g_vt[(size_t)NKV * HD * SEQ];    // V transposed [c][s], tf32

__device__ __forceinline__ uint32_t cvt_tf32(float x) {
    uint32_t r;
    asm("cvt.rna.tf32.f32 %0, %1;" : "=r"(r) : "f"(x));
    return r;
}
__device__ __forceinline__ float tf32f(float x) { return __uint_as_float(cvt_tf32(x)); }
__device__ __forceinline__ void ldm4(uint32_t* r, uint32_t addr) {
    asm volatile("ldmatrix.sync.aligned.m8n8.x4.shared.b16 {%0,%1,%2,%3}, [%4];"
                 : "=r"(r[0]), "=r"(r[1]), "=r"(r[2]), "=r"(r[3]) : "r"(addr));
}
__device__ __forceinline__ void mma8(float* c, const uint32_t* a, uint32_t b0, uint32_t b1) {
    asm volatile("mma.sync.aligned.m16n8k8.row.col.f32.tf32.tf32.f32 "
                 "{%0,%1,%2,%3}, {%4,%5,%6,%7}, {%8,%9}, {%0,%1,%2,%3};"
                 : "+f"(c[0]), "+f"(c[1]), "+f"(c[2]), "+f"(c[3])
                 : "r"(a[0]), "r"(a[1]), "r"(a[2]), "r"(a[3]), "r"(b0), "r"(b1));
}
__device__ __forceinline__ void mma16(float* c, const uint32_t* a, uint32_t b0, uint32_t b1) {
    asm volatile("mma.sync.aligned.m16n8k16.row.col.f32.bf16.bf16.f32 "
                 "{%0,%1,%2,%3}, {%4,%5,%6,%7}, {%8,%9}, {%0,%1,%2,%3};"
                 : "+f"(c[0]), "+f"(c[1]), "+f"(c[2]), "+f"(c[3])
                 : "r"(a[0]), "r"(a[1]), "r"(a[2]), "r"(a[3]), "r"(b0), "r"(b1));
}
__device__ __forceinline__ uint32_t pack2bf(float a, float b) {
    __nv_bfloat162 t = __floats2bfloat162_rn(a, b);
    return *(uint32_t*)&t;
}
__device__ __forceinline__ float bfhi(float a) {
    return __bfloat162float(__float2bfloat16(a));
}

// ---------------- prepass: rna-round fp32 to tf32 values ----------------
__global__ void cvt_rna(const float* __restrict__ in, float* __restrict__ out, int n4)
{
    int i = blockIdx.x * blockDim.x + threadIdx.x;
    if (i >= n4) return;
    float4 v = ((const float4*)in)[i];
    v.x = tf32f(v.x); v.y = tf32f(v.y); v.z = tf32f(v.z); v.w = tf32f(v.w);
    ((float4*)out)[i] = v;
}

// ---------------- TF32 NT GEMM (R10 best config, unchanged) ----------------------
#define SA 36
#define ASTG (128 * SA)
#define BSTG (256 * SA)
#define GSTG (ASTG + BSTG)
#define GSMEM_BYTES (2 * GSTG * 4)   // 110592

__global__ __launch_bounds__(256, 1) void gemm_tf32(const float* __restrict__ A,
                                                    const float* __restrict__ B0,
                                                    const float* __restrict__ B1,
                                                    const float* __restrict__ B2,
                                                    float* __restrict__ C,
                                                    int M, int outN, int K)
{
    extern __shared__ float sh[];
    int tid = threadIdx.x;
    int wid = tid >> 5, lane = tid & 31;
    int warp_m = wid >> 2, warp_n = wid & 3;
    int m0 = blockIdx.y * 128, n0 = blockIdx.x * 256;

    const float* Bsel;
    int nloc;
    if (n0 < DIM)                { Bsel = B0; nloc = n0; }
    else if (n0 < DIM + 1024)    { Bsel = B1; nloc = n0 - DIM; }
    else                         { Bsel = B2; nloc = n0 - DIM - 1024; }

    int lr = tid >> 3;
    int lc = (tid & 7) * 4;
    const float* Aq = A + (size_t)(m0 + lr) * K + lc;
    const float* Bq = Bsel + (size_t)(nloc + lr) * K + lc;

    float4 ra[4], rb[8];
    uint32_t shbase = (uint32_t)__cvta_generic_to_shared(sh);

    int la = lane & 15, ahi = lane >> 4;
    int rbv = (lane & 7) + ((lane >> 4) << 3), bhiv = (lane >> 3) & 1;
    uint32_t a_addr[4], b_addr[4];
#pragma unroll
    for (int mi = 0; mi < 4; mi++)
        a_addr[mi] = shbase + (uint32_t)(((warp_m * 64 + mi * 16 + la) * SA + ahi * 4) << 2);
#pragma unroll
    for (int nb = 0; nb < 4; nb++)
        b_addr[nb] = shbase + (uint32_t)((ASTG + (warp_n * 64 + nb * 16 + rbv) * SA + bhiv * 4) << 2);

    float acc[4][8][4];
#pragma unroll
    for (int mi = 0; mi < 4; mi++)
#pragma unroll
        for (int ni = 0; ni < 8; ni++)
#pragma unroll
            for (int t = 0; t < 4; t++) acc[mi][ni][t] = 0.0f;

    const int iters = K >> 5;

    auto store_stage = [&](int s) {
        float* As = sh + s * GSTG;
        float* Bs = As + ASTG;
#pragma unroll
        for (int rr = 0; rr < 4; rr++)
            *(float4*)&As[(lr + 32 * rr) * SA + lc] = ra[rr];
#pragma unroll
        for (int rr = 0; rr < 8; rr++)
            *(float4*)&Bs[(lr + 32 * rr) * SA + lc] = rb[rr];
    };

#pragma unroll
    for (int rr = 0; rr < 4; rr++) ra[rr] = *(const float4*)(Aq + (size_t)rr * 32 * K);
#pragma unroll
    for (int rr = 0; rr < 8; rr++) rb[rr] = *(const float4*)(Bq + (size_t)rr * 32 * K);
    store_stage(0);
    __syncthreads();

    for (int it = 0; it < iters; ++it) {
        int cur = it & 1;
        if (it + 1 < iters) {
            int ko = (it + 1) << 5;
#pragma unroll
            for (int rr = 0; rr < 4; rr++)
                ra[rr] = *(const float4*)(Aq + (size_t)rr * 32 * K + ko);
#pragma unroll
            for (int rr = 0; rr < 8; rr++)
                rb[rr] = *(const float4*)(Bq + (size_t)rr * 32 * K + ko);
        }

        uint32_t boff = (uint32_t)(cur * GSTG * 4);
#pragma unroll
        for (int ks = 0; ks < 4; ks++) {
            uint32_t af[4][4], bf[4][4];
#pragma unroll
            for (int mi = 0; mi < 4; mi++) ldm4(af[mi], a_addr[mi] + boff + ks * 32);
#pragma unroll
            for (int nb = 0; nb < 4; nb++) ldm4(bf[nb], b_addr[nb] + boff + ks * 32);
#pragma unroll
            for (int mi = 0; mi < 4; mi++)
#pragma unroll
                for (int nb = 0; nb < 4; nb++) {
                    mma8(acc[mi][2 * nb],     af[mi], bf[nb][0], bf[nb][1]);
                    mma8(acc[mi][2 * nb + 1], af[mi], bf[nb][2], bf[nb][3]);
                }
        }

        if (it + 1 < iters) {
            store_stage(cur ^ 1);
            __syncthreads();
        }
    }

    int g = lane >> 2, tg = lane & 3;
#pragma unroll
    for (int mi = 0; mi < 4; mi++) {
#pragma unroll
        for (int ni = 0; ni < 8; ni++) {
            int row = m0 + warp_m * 64 + mi * 16 + g;
            int col = n0 + warp_n * 64 + ni * 8 + tg * 2;
            *(float2*)&C[(size_t)row * outN + col] =
                make_float2(acc[mi][ni][0], acc[mi][ni][1]);
            *(float2*)&C[(size_t)(row + 8) * outN + col] =
                make_float2(acc[mi][ni][2], acc[mi][ni][3]);
        }
    }
}

// ---------------- RoPE + operand-format prepasses ----------------
__global__ void rope_q_prep(const float* __restrict__ qkv, const float* __restrict__ cs,
                            const float* __restrict__ sn,
                            uint32_t* __restrict__ qh, uint32_t* __restrict__ ql)
{
    const float scale = 0.08838834764831845f;
    int idx = blockIdx.x * blockDim.x + threadIdx.x;
    if (idx >= SEQ * NH * 64) return;
    int pr = idx & 63;
    int hh = (idx >> 6) & 31;
    int ss = idx >> 11;
    float c = cs[ss * 64 + pr], si = sn[ss * 64 + pr];
    float2 ri = *(const float2*)&qkv[(size_t)ss * QKVN + hh * HD + 2 * pr];
    float ox = (ri.x * c - ri.y * si) * scale;
    float oy = (ri.x * si + ri.y * c) * scale;
    float hx = bfhi(ox), hy = bfhi(oy);
    size_t w = ((size_t)hh * SEQ + ss) * 64 + pr;
    qh[w] = pack2bf(hx, hy);
    ql[w] = pack2bf(ox - hx, oy - hy);
}

__global__ void rope_k_prep(const float* __restrict__ qkv, const float* __restrict__ cs,
                            const float* __restrict__ sn,
                            uint32_t* __restrict__ kh, uint32_t* __restrict__ kl)
{
    int idx = blockIdx.x * blockDim.x + threadIdx.x;
    if (idx >= SEQ * NKV * 64) return;
    int pr = idx & 63;
    int hh = (idx >> 6) & 7;
    int ss = idx >> 9;
    float c = cs[ss * 64 + pr], si = sn[ss * 64 + pr];
    float2 ri = *(const float2*)&qkv[(size_t)ss * QKVN + DIM + hh * HD + 2 * pr];
    float ox = ri.x * c - ri.y * si;
    float oy = ri.x * si + ri.y * c;
    float hx = bfhi(ox), hy = bfhi(oy);
    size_t w = ((size_t)hh * SEQ + ss) * 64 + pr;
    kh[w] = pack2bf(hx, hy);
    kl[w] = pack2bf(ox - hx, oy - hy);
}

// V transpose: [s][c] -> [c][s], tf32-rounded
__global__ void v_prep(const float* __restrict__ qkv, float* __restrict__ vt)
{
    __shared__ float t[32][33];
    int s0 = blockIdx.x * 32, c0 = blockIdx.y * 32;
    int tx = threadIdx.x, ty = threadIdx.y;
#pragma unroll
    for (int j = 0; j < 32; j += 8)
        t[ty + j][tx] = qkv[(size_t)(s0 + ty + j) * QKVN + DIM + 1024 + c0 + tx];
    __syncthreads();
#pragma unroll
    for (int j = 0; j < 32; j += 8)
        vt[(size_t)(c0 + ty + j) * SEQ + s0 + tx] = tf32f(t[tx][ty + j]);
}

// ---------------- Flash attention: warp-m32 (4 warps), cp.async pipelined --------
#define AQH 0
#define AQL 8704
#define AKH 17408
#define AKL 26112
#define KSTG 4352
#define AVT 34816
#define APS 43520
#define ATT_WORDS 52224    // 208896 bytes

__global__ __launch_bounds__(128, 1) void attn_tc(const uint32_t* __restrict__ qh,
                                                  const uint32_t* __restrict__ ql,
                                                  const uint32_t* __restrict__ kh,
                                                  const uint32_t* __restrict__ kl,
                                                  const float* __restrict__ vt,
                                                  float* __restrict__ O)
{
    extern __shared__ float sm[];
    int tid = threadIdx.x, wid = tid >> 5, lane = tid & 31;
    int qt = (int)gridDim.x - 1 - (int)blockIdx.x;   // longest-first
    int h = blockIdx.y, kvh = h >> 2;
    int qm0 = qt * 128;
    int g = lane >> 2, tg = lane & 3;
    int wr0 = wid * 32;                               // warp covers m32

    uint32_t shb = (uint32_t)__cvta_generic_to_shared(sm);

    // ---- prologue: issue Q tile + K tile 0 ----
    {
        const uint32_t* qsrc_h = qh + ((size_t)h * SEQ + qm0) * 64;
        const uint32_t* qsrc_l = ql + ((size_t)h * SEQ + qm0) * 64;
        for (int i = tid; i < 2048; i += 128) {
            int r = i >> 4, ch = (i & 15) * 4;
            asm volatile("cp.async.cg.shared.global [%0], [%1], 16;"
                         :: "r"(shb + ((AQH + r * 68 + ch) << 2)), "l"(qsrc_h + r * 64 + ch));
            asm volatile("cp.async.cg.shared.global [%0], [%1], 16;"
                         :: "r"(shb + ((AQL + r * 68 + ch) << 2)), "l"(qsrc_l + r * 64 + ch));
        }
        const uint32_t* ksrc_h = kh + (size_t)kvh * SEQ * 64;
        const uint32_t* ksrc_l = kl + (size_t)kvh * SEQ * 64;
        for (int i = tid; i < 1024; i += 128) {
            int r = i >> 4, ch = (i & 15) * 4;
            asm volatile("cp.async.cg.shared.global [%0], [%1], 16;"
                         :: "r"(shb + ((AKH + r * 68 + ch) << 2)), "l"(ksrc_h + r * 64 + ch));
            asm volatile("cp.async.cg.shared.global [%0], [%1], 16;"
                         :: "r"(shb + ((AKL + r * 68 + ch) << 2)), "l"(ksrc_l + r * 64 + ch));
        }
        asm volatile("cp.async.commit_group;");
    }

    int la = lane & 15, hiq = lane >> 4;
    uint32_t aQH[2], aQL[2], aP[2];
#pragma unroll
    for (int mi = 0; mi < 2; mi++) {
        aQH[mi] = shb + (uint32_t)((AQH + (wr0 + mi * 16 + la) * 68 + hiq * 4) << 2);
        aQL[mi] = shb + (uint32_t)((AQL + (wr0 + mi * 16 + la) * 68 + hiq * 4) << 2);
        aP[mi]  = shb + (uint32_t)((APS + (wr0 + mi * 16 + la) * 68 + hiq * 4) << 2);
    }
    uint32_t bKHb = shb + (uint32_t)((AKH + la * 68 + hiq * 4) << 2);
    uint32_t bKLb = shb + (uint32_t)((AKL + la * 68 + hiq * 4) << 2);
    int rbv = (lane & 7) + ((lane >> 4) << 3), bhiv = (lane >> 3) & 1;
    uint32_t bV = shb + (uint32_t)((AVT + rbv * 68 + bhiv * 4) << 2);

    // oa[nf][mi][4]: comps 0,1 -> row g; 2,3 -> row g+8 (within mi*16 group)
    float oa[16][2][4];
#pragma unroll
    for (int i = 0; i < 16; i++)
#pragma unroll
        for (int mi = 0; mi < 2; mi++)
#pragma unroll
            for (int j = 0; j < 4; j++) oa[i][mi][j] = 0.0f;
    float m_s[2][2], l_s[2][2];
#pragma unroll
    for (int mi = 0; mi < 2; mi++) {
        m_s[mi][0] = -1e30f; m_s[mi][1] = -1e30f;
        l_s[mi][0] = 0.0f;   l_s[mi][1] = 0.0f;
    }

    int ktmax = 2 * qt + 1;
    const uint32_t* ksrc_h = kh + (size_t)kvh * SEQ * 64;
    const uint32_t* ksrc_l = kl + (size_t)kvh * SEQ * 64;
    const float*    vsrc   = vt + (size_t)kvh * HD * SEQ;

    for (int kt = 0; kt <= ktmax; kt++) {
        int kn0 = kt * 64;
        int st = kt & 1;
        uint32_t stoff = (uint32_t)(st * KSTG * 4);

        __syncthreads();   // V buffer + next K stage free

        for (int i = tid; i < 2048; i += 128) {
            int c = i >> 4, ch = (i & 15) * 4;
            asm volatile("cp.async.cg.shared.global [%0], [%1], 16;"
                         :: "r"(shb + ((AVT + c * 68 + ch) << 2)),
                            "l"(vsrc + (size_t)c * SEQ + kn0 + ch));
        }
        asm volatile("cp.async.commit_group;");

        if (kt < ktmax) {
            uint32_t nstoff = (uint32_t)((st ^ 1) * KSTG * 4);
            int kn1 = kn0 + 64;
            for (int i = tid; i < 1024; i += 128) {
                int r = i >> 4, ch = (i & 15) * 4;
                asm volatile("cp.async.cg.shared.global [%0], [%1], 16;"
                             :: "r"(shb + ((AKH + r * 68 + ch) << 2) + nstoff),
                                "l"(ksrc_h + (size_t)(kn1 + r) * 64 + ch));
                asm volatile("cp.async.cg.shared.global [%0], [%1], 16;"
                             :: "r"(shb + ((AKL + r * 68 + ch) << 2) + nstoff),
                                "l"(ksrc_l + (size_t)(kn1 + r) * 64 + ch));
            }
        }
        asm volatile("cp.async.commit_group;");

        asm volatile("cp.async.wait_group 2;");   // K(kt) (and Q) ready
        __syncthreads();

        bool skip = (qm0 + wr0 + 31 < kn0);
        float sc[8][2][4];

        if (!skip) {
            // ---- QK^T: bf16 hi/lo 3-term, m32 per warp ----
#pragma unroll
            for (int i = 0; i < 8; i++)
#pragma unroll
                for (int mi = 0; mi < 2; mi++)
#pragma unroll
                    for (int j = 0; j < 4; j++) sc[i][mi][j] = 0.0f;

#pragma unroll 2
            for (int ks = 0; ks < 8; ks++) {
                uint32_t ah[2][4], al[2][4];
#pragma unroll
                for (int mi = 0; mi < 2; mi++) {
                    ldm4(ah[mi], aQH[mi] + ks * 32);
                    ldm4(al[mi], aQL[mi] + ks * 32);
                }
#pragma unroll
                for (int npp = 0; npp < 4; npp++) {
                    uint32_t bh[4], bl[4];
                    ldm4(bh, bKHb + stoff + (uint32_t)(npp * 16 * 68 * 4) + ks * 32);
                    ldm4(bl, bKLb + stoff + (uint32_t)(npp * 16 * 68 * 4) + ks * 32);
#pragma unroll
                    for (int mi = 0; mi < 2; mi++) {
                        mma16(sc[2 * npp][mi],     ah[mi], bh[0], bh[2]);
                        mma16(sc[2 * npp][mi],     al[mi], bh[0], bh[2]);
                        mma16(sc[2 * npp][mi],     ah[mi], bl[0], bl[2]);
                        mma16(sc[2 * npp + 1][mi], ah[mi], bh[1], bh[3]);
                        mma16(sc[2 * npp + 1][mi], al[mi], bh[1], bh[3]);
                        mma16(sc[2 * npp + 1][mi], ah[mi], bl[1], bl[3]);
                    }
                }
            }

            // causal mask on diagonal tiles
            if (kt >= 2 * qt) {
#pragma unroll
                for (int nf = 0; nf < 8; nf++) {
                    int kc = kn0 + nf * 8 + 2 * tg;
#pragma unroll
                    for (int mi = 0; mi < 2; mi++) {
                        int r0 = qm0 + wr0 + mi * 16 + g;
                        if (kc > r0)         sc[nf][mi][0] = -1e30f;
                        if (kc + 1 > r0)     sc[nf][mi][1] = -1e30f;
                        if (kc > r0 + 8)     sc[nf][mi][2] = -1e30f;
                        if (kc + 1 > r0 + 8) sc[nf][mi][3] = -1e30f;
                    }
                }
            }

            // ---- online softmax (4 rows per thread) ----
#pragma unroll
            for (int mi = 0; mi < 2; mi++) {
                float rm0 = -1e30f, rm1 = -1e30f;
#pragma unroll
                for (int nf = 0; nf < 8; nf++) {
                    rm0 = fmaxf(rm0, fmaxf(sc[nf][mi][0], sc[nf][mi][1]));
                    rm1 = fmaxf(rm1, fmaxf(sc[nf][mi][2], sc[nf][mi][3]));
                }
                rm0 = fmaxf(rm0, __shfl_xor_sync(0xffffffffu, rm0, 1));
                rm0 = fmaxf(rm0, __shfl_xor_sync(0xffffffffu, rm0, 2));
                rm1 = fmaxf(rm1, __shfl_xor_sync(0xffffffffu, rm1, 1));
                rm1 = fmaxf(rm1, __shfl_xor_sync(0xffffffffu, rm1, 2));
                float mn0 = fmaxf(m_s[mi][0], rm0), mn1 = fmaxf(m_s[mi][1], rm1);
                float fac0 = __expf(m_s[mi][0] - mn0), fac1 = __expf(m_s[mi][1] - mn1);
                float rs0 = 0.0f, rs1 = 0.0f;
#pragma unroll
                for (int nf = 0; nf < 8; nf++) {
                    sc[nf][mi][0] = __expf(sc[nf][mi][0] - mn0);
                    sc[nf][mi][1] = __expf(sc[nf][mi][1] - mn0);
                    sc[nf][mi][2] = __expf(sc[nf][mi][2] - mn1);
                    sc[nf][mi][3] = __expf(sc[nf][mi][3] - mn1);
                    rs0 += sc[nf][mi][0] + sc[nf][mi][1];
                    rs1 += sc[nf][mi][2] + sc[nf][mi][3];
                }
                rs0 += __shfl_xor_sync(0xffffffffu, rs0, 1);
                rs0 += __shfl_xor_sync(0xffffffffu, rs0, 2);
                rs1 += __shfl_xor_sync(0xffffffffu, rs1, 1);
                rs1 += __shfl_xor_sync(0xffffffffu, rs1, 2);
                l_s[mi][0] = l_s[mi][0] * fac0 + rs0; m_s[mi][0] = mn0;
                l_s[mi][1] = l_s[mi][1] * fac1 + rs1; m_s[mi][1] = mn1;
#pragma unroll
                for (int nf = 0; nf < 16; nf++) {
                    oa[nf][mi][0] *= fac0; oa[nf][mi][1] *= fac0;
                    oa[nf][mi][2] *= fac1; oa[nf][mi][3] *= fac1;
                }
            }
        }

        asm volatile("cp.async.wait_group 1;");   // V(kt) ready
        __syncthreads();

        if (!skip) {
            // write P (tf32) to warp-private smem rows
#pragma unroll
            for (int mi = 0; mi < 2; mi++)
#pragma unroll
                for (int nf = 0; nf < 8; nf++) {
                    *(float2*)&sm[APS + (wr0 + mi * 16 + g) * 68 + nf * 8 + 2 * tg] =
                        make_float2(tf32f(sc[nf][mi][0]), tf32f(sc[nf][mi][1]));
                    *(float2*)&sm[APS + (wr0 + mi * 16 + g + 8) * 68 + nf * 8 + 2 * tg] =
                        make_float2(tf32f(sc[nf][mi][2]), tf32f(sc[nf][mi][3]));
                }
            __syncwarp();

            // ---- O += P @ V (tf32) ----
#pragma unroll 2
            for (int ks2 = 0; ks2 < 8; ks2++) {
                uint32_t pa[2][4];
                ldm4(pa[0], aP[0] + ks2 * 32);
                ldm4(pa[1], aP[1] + ks2 * 32);
#pragma unroll
                for (int np = 0; np < 8; np++) {
                    uint32_t bv[4];
                    ldm4(bv, bV + (uint32_t)(np * 16 * 68 * 4) + ks2 * 32);
#pragma unroll
                    for (int mi = 0; mi < 2; mi++) {
                        mma8(oa[2 * np][mi],     pa[mi], bv[0], bv[1]);
                        mma8(oa[2 * np + 1][mi], pa[mi], bv[2], bv[3]);
                    }
                }
            }
        }
    }

    // epilogue: rna-rounded att (O-proj A operand is pre-rounded)
#pragma unroll
    for (int mi = 0; mi < 2; mi++) {
        float inv0 = 1.0f / l_s[mi][0], inv1 = 1.0f / l_s[mi][1];
        int r0 = qm0 + wr0 + mi * 16 + g;
#pragma unroll
        for (int nf = 0; nf < 16; nf++) {
            int col = nf * 8 + 2 * tg;
            *(float2*)&O[((size_t)r0 * NH + h) * HD + col] =
                make_float2(tf32f(oa[nf][mi][0] * inv0), tf32f(oa[nf][mi][1] * inv0));
            *(float2*)&O[((size_t)(r0 + 8) * NH + h) * HD + col] =
                make_float2(tf32f(oa[nf][mi][2] * inv1), tf32f(oa[nf][mi][3] * inv1));
        }
    }
}

// ---------------- launch ----------------
extern "C" void kernel_launch(void* const* d_in, const int* in_sizes, int n_in,
                              void* d_out, int out_size)
{
    const float* x  = (const float*)d_in[0];
    const float* wq = (const float*)d_in[1];
    const float* wk = (const float*)d_in[2];
    const float* wv = (const float*)d_in[3];
    const float* wo = (const float*)d_in[4];
    const float* fc = (const float*)d_in[5];
    const float* fs = (const float*)d_in[6];
    float* out = (float*)d_out;

    float *qkv, *att, *vtb, *xc, *wqc, *wkc, *wvc, *woc;
    uint32_t *qhb, *qlb, *khb, *klb;
    cudaGetSymbolAddress((void**)&qkv, g_qkv);
    cudaGetSymbolAddress((void**)&att, g_att);
    cudaGetSymbolAddress((void**)&xc,  g_xc);
    cudaGetSymbolAddress((void**)&wqc, g_wqc);
    cudaGetSymbolAddress((void**)&wkc, g_wkc);
    cudaGetSymbolAddress((void**)&wvc, g_wvc);
    cudaGetSymbolAddress((void**)&woc, g_woc);
    cudaGetSymbolAddress((void**)&qhb, g_qh);
    cudaGetSymbolAddress((void**)&qlb, g_ql);
    cudaGetSymbolAddress((void**)&khb, g_kh);
    cudaGetSymbolAddress((void**)&klb, g_kl);
    cudaGetSymbolAddress((void**)&vtb, g_vt);

    int t = 256;
    cvt_rna<<<(SEQ * DIM / 4 + t - 1) / t, t>>>(x, xc, SEQ * DIM / 4);
    cvt_rna<<<(DIM * DIM / 4 + t - 1) / t, t>>>(wq, wqc, DIM * DIM / 4);
    cvt_rna<<<(1024 * DIM / 4 + t - 1) / t, t>>>(wk, wkc, 1024 * DIM / 4);
    cvt_rna<<<(1024 * DIM / 4 + t - 1) / t, t>>>(wv, wvc, 1024 * DIM / 4);
    cvt_rna<<<(DIM * DIM / 4 + t - 1) / t, t>>>(wo, woc, DIM * DIM / 4);

    cudaFuncSetAttribute(gemm_tf32, cudaFuncAttributeMaxDynamicSharedMemorySize, GSMEM_BYTES);

    dim3 blk(256);
    gemm_tf32<<<dim3(QKVN / 256, SEQ / 128), blk, GSMEM_BYTES>>>(xc, wqc, wkc, wvc, qkv, SEQ, QKVN, DIM);

    rope_q_prep<<<(SEQ * NH * 64 + 255) / 256, 256>>>(qkv, fc, fs, qhb, qlb);
    rope_k_prep<<<(SEQ * NKV * 64 + 255) / 256, 256>>>(qkv, fc, fs, khb, klb);
    v_prep<<<dim3(SEQ / 32, 1024 / 32), dim3(32, 8)>>>(qkv, vtb);

    int ash = ATT_WORDS * (int)sizeof(float);
    cudaFuncSetAttribute(attn_tc, cudaFuncAttributeMaxDynamicSharedMemorySize, ash);
    attn_tc<<<dim3(SEQ / 128, NH), 128, ash>>>(qhb, qlb, khb, klb, vtb, att);

    gemm_tf32<<<dim3(DIM / 256, SEQ / 128), blk, GSMEM_BYTES>>>(att, woc, woc, woc, out, SEQ, DIM, DIM);
}

// round 14
// speedup vs baseline: 1.1733x; 1.1002x over previous
#include <cuda_runtime.h>
#include <cuda_bf16.h>
#include <cuda_fp16.h>
#include <cstdint>

#define SEQ 2048
#define DIM 4096
#define NH  32
#define NKV 8
#define HD  128
#define QKVN 6144   // fused projection N (4096 q + 1024 k + 1024 v)

// ---------------- scratch (device globals: no allocation allowed) ----------------
__device__ float    g_qkv[(size_t)SEQ * QKVN];       // fused q|k|v (fp32)
__device__ float    g_att[(size_t)SEQ * DIM];        // attention out (rna-rounded)
__device__ float    g_xc[(size_t)SEQ * DIM];         // rna-rounded x
__device__ float    g_wqc[(size_t)DIM * DIM];        // rna-rounded wq
__device__ float    g_wkc[(size_t)1024 * DIM];       // rna-rounded wk
__device__ float    g_wvc[(size_t)1024 * DIM];       // rna-rounded wv
__device__ float    g_woc[(size_t)DIM * DIM];        // rna-rounded wo
__device__ uint32_t g_qh[(size_t)NH  * SEQ * 64];    // Q hi  bf16x2 (scaled, roped)
__device__ uint32_t g_ql[(size_t)NH  * SEQ * 64];    // Q lo  bf16x2
__device__ uint32_t g_kh[(size_t)NKV * SEQ * 64];    // K hi  bf16x2 (roped)
__device__ uint32_t g_kl[(size_t)NKV * SEQ * 64];    // K lo  bf16x2
__device__ uint32_t g_vt[(size_t)NKV * HD * SEQ / 2]; // V transposed [c][s], half2

__device__ __forceinline__ uint32_t cvt_tf32(float x) {
    uint32_t r;
    asm("cvt.rna.tf32.f32 %0, %1;" : "=r"(r) : "f"(x));
    return r;
}
__device__ __forceinline__ float tf32f(float x) { return __uint_as_float(cvt_tf32(x)); }
__device__ __forceinline__ void ldm4(uint32_t* r, uint32_t addr) {
    asm volatile("ldmatrix.sync.aligned.m8n8.x4.shared.b16 {%0,%1,%2,%3}, [%4];"
                 : "=r"(r[0]), "=r"(r[1]), "=r"(r[2]), "=r"(r[3]) : "r"(addr));
}
__device__ __forceinline__ void mma8(float* c, const uint32_t* a, uint32_t b0, uint32_t b1) {
    asm volatile("mma.sync.aligned.m16n8k8.row.col.f32.tf32.tf32.f32 "
                 "{%0,%1,%2,%3}, {%4,%5,%6,%7}, {%8,%9}, {%0,%1,%2,%3};"
                 : "+f"(c[0]), "+f"(c[1]), "+f"(c[2]), "+f"(c[3])
                 : "r"(a[0]), "r"(a[1]), "r"(a[2]), "r"(a[3]), "r"(b0), "r"(b1));
}
__device__ __forceinline__ void mma16(float* c, const uint32_t* a, uint32_t b0, uint32_t b1) {
    asm volatile("mma.sync.aligned.m16n8k16.row.col.f32.bf16.bf16.f32 "
                 "{%0,%1,%2,%3}, {%4,%5,%6,%7}, {%8,%9}, {%0,%1,%2,%3};"
                 : "+f"(c[0]), "+f"(c[1]), "+f"(c[2]), "+f"(c[3])
                 : "r"(a[0]), "r"(a[1]), "r"(a[2]), "r"(a[3]), "r"(b0), "r"(b1));
}
__device__ __forceinline__ void mma16h(float* c, const uint32_t* a, uint32_t b0, uint32_t b1) {
    asm volatile("mma.sync.aligned.m16n8k16.row.col.f32.f16.f16.f32 "
                 "{%0,%1,%2,%3}, {%4,%5,%6,%7}, {%8,%9}, {%0,%1,%2,%3};"
                 : "+f"(c[0]), "+f"(c[1]), "+f"(c[2]), "+f"(c[3])
                 : "r"(a[0]), "r"(a[1]), "r"(a[2]), "r"(a[3]), "r"(b0), "r"(b1));
}
__device__ __forceinline__ uint32_t pack2bf(float a, float b) {
    __nv_bfloat162 t = __floats2bfloat162_rn(a, b);
    return *(uint32_t*)&t;
}
__device__ __forceinline__ uint32_t pack2h(float a, float b) {
    __half2 t = __floats2half2_rn(a, b);
    return *(uint32_t*)&t;
}
__device__ __forceinline__ float bfhi(float a) {
    return __bfloat162float(__float2bfloat16(a));
}

// ---------------- prepass: rna-round fp32, MLP=4 (n4 must divide threads*4) ------
__global__ void cvt_rna(const float* __restrict__ in, float* __restrict__ out, int n4)
{
    int stride = gridDim.x * blockDim.x;
    int i = blockIdx.x * blockDim.x + threadIdx.x;
    float4 v0 = ((const float4*)in)[i];
    float4 v1 = ((const float4*)in)[i + stride];
    float4 v2 = ((const float4*)in)[i + 2 * stride];
    float4 v3 = ((const float4*)in)[i + 3 * stride];
    v0.x = tf32f(v0.x); v0.y = tf32f(v0.y); v0.z = tf32f(v0.z); v0.w = tf32f(v0.w);
    v1.x = tf32f(v1.x); v1.y = tf32f(v1.y); v1.z = tf32f(v1.z); v1.w = tf32f(v1.w);
    v2.x = tf32f(v2.x); v2.y = tf32f(v2.y); v2.z = tf32f(v2.z); v2.w = tf32f(v2.w);
    v3.x = tf32f(v3.x); v3.y = tf32f(v3.y); v3.z = tf32f(v3.z); v3.w = tf32f(v3.w);
    ((float4*)out)[i] = v0;
    ((float4*)out)[i + stride] = v1;
    ((float4*)out)[i + 2 * stride] = v2;
    ((float4*)out)[i + 3 * stride] = v3;
}

// ---------------- TF32 NT GEMM (R10 best config, unchanged) ----------------------
#define SA 36
#define ASTG (128 * SA)
#define BSTG (256 * SA)
#define GSTG (ASTG + BSTG)
#define GSMEM_BYTES (2 * GSTG * 4)   // 110592

__global__ __launch_bounds__(256, 1) void gemm_tf32(const float* __restrict__ A,
                                                    const float* __restrict__ B0,
                                                    const float* __restrict__ B1,
                                                    const float* __restrict__ B2,
                                                    float* __restrict__ C,
                                                    int M, int outN, int K)
{
    extern __shared__ float sh[];
    int tid = threadIdx.x;
    int wid = tid >> 5, lane = tid & 31;
    int warp_m = wid >> 2, warp_n = wid & 3;
    int m0 = blockIdx.y * 128, n0 = blockIdx.x * 256;

    const float* Bsel;
    int nloc;
    if (n0 < DIM)                { Bsel = B0; nloc = n0; }
    else if (n0 < DIM + 1024)    { Bsel = B1; nloc = n0 - DIM; }
    else                         { Bsel = B2; nloc = n0 - DIM - 1024; }

    int lr = tid >> 3;
    int lc = (tid & 7) * 4;
    const float* Aq = A + (size_t)(m0 + lr) * K + lc;
    const float* Bq = Bsel + (size_t)(nloc + lr) * K + lc;

    float4 ra[4], rb[8];
    uint32_t shbase = (uint32_t)__cvta_generic_to_shared(sh);

    int la = lane & 15, ahi = lane >> 4;
    int rbv = (lane & 7) + ((lane >> 4) << 3), bhiv = (lane >> 3) & 1;
    uint32_t a_addr[4], b_addr[4];
#pragma unroll
    for (int mi = 0; mi < 4; mi++)
        a_addr[mi] = shbase + (uint32_t)(((warp_m * 64 + mi * 16 + la) * SA + ahi * 4) << 2);
#pragma unroll
    for (int nb = 0; nb < 4; nb++)
        b_addr[nb] = shbase + (uint32_t)((ASTG + (warp_n * 64 + nb * 16 + rbv) * SA + bhiv * 4) << 2);

    float acc[4][8][4];
#pragma unroll
    for (int mi = 0; mi < 4; mi++)
#pragma unroll
        for (int ni = 0; ni < 8; ni++)
#pragma unroll
            for (int t = 0; t < 4; t++) acc[mi][ni][t] = 0.0f;

    const int iters = K >> 5;

    auto store_stage = [&](int s) {
        float* As = sh + s * GSTG;
        float* Bs = As + ASTG;
#pragma unroll
        for (int rr = 0; rr < 4; rr++)
            *(float4*)&As[(lr + 32 * rr) * SA + lc] = ra[rr];
#pragma unroll
        for (int rr = 0; rr < 8; rr++)
            *(float4*)&Bs[(lr + 32 * rr) * SA + lc] = rb[rr];
    };

#pragma unroll
    for (int rr = 0; rr < 4; rr++) ra[rr] = *(const float4*)(Aq + (size_t)rr * 32 * K);
#pragma unroll
    for (int rr = 0; rr < 8; rr++) rb[rr] = *(const float4*)(Bq + (size_t)rr * 32 * K);
    store_stage(0);
    __syncthreads();

    for (int it = 0; it < iters; ++it) {
        int cur = it & 1;
        if (it + 1 < iters) {
            int ko = (it + 1) << 5;
#pragma unroll
            for (int rr = 0; rr < 4; rr++)
                ra[rr] = *(const float4*)(Aq + (size_t)rr * 32 * K + ko);
#pragma unroll
            for (int rr = 0; rr < 8; rr++)
                rb[rr] = *(const float4*)(Bq + (size_t)rr * 32 * K + ko);
        }

        uint32_t boff = (uint32_t)(cur * GSTG * 4);
#pragma unroll
        for (int ks = 0; ks < 4; ks++) {
            uint32_t af[4][4], bf[4][4];
#pragma unroll
            for (int mi = 0; mi < 4; mi++) ldm4(af[mi], a_addr[mi] + boff + ks * 32);
#pragma unroll
            for (int nb = 0; nb < 4; nb++) ldm4(bf[nb], b_addr[nb] + boff + ks * 32);
#pragma unroll
            for (int mi = 0; mi < 4; mi++)
#pragma unroll
                for (int nb = 0; nb < 4; nb++) {
                    mma8(acc[mi][2 * nb],     af[mi], bf[nb][0], bf[nb][1]);
                    mma8(acc[mi][2 * nb + 1], af[mi], bf[nb][2], bf[nb][3]);
                }
        }

        if (it + 1 < iters) {
            store_stage(cur ^ 1);
            __syncthreads();
        }
    }

    int g = lane >> 2, tg = lane & 3;
#pragma unroll
    for (int mi = 0; mi < 4; mi++) {
#pragma unroll
        for (int ni = 0; ni < 8; ni++) {
            int row = m0 + warp_m * 64 + mi * 16 + g;
            int col = n0 + warp_n * 64 + ni * 8 + tg * 2;
            *(float2*)&C[(size_t)row * outN + col] =
                make_float2(acc[mi][ni][0], acc[mi][ni][1]);
            *(float2*)&C[(size_t)(row + 8) * outN + col] =
                make_float2(acc[mi][ni][2], acc[mi][ni][3]);
        }
    }
}

// ---------------- RoPE + operand-format prepasses ----------------
__global__ void rope_q_prep(const float* __restrict__ qkv, const float* __restrict__ cs,
                            const float* __restrict__ sn,
                            uint32_t* __restrict__ qh, uint32_t* __restrict__ ql)
{
    const float scale = 0.08838834764831845f;
    int idx = blockIdx.x * blockDim.x + threadIdx.x;
    if (idx >= SEQ * NH * 64) return;
    int pr = idx & 63;
    int hh = (idx >> 6) & 31;
    int ss = idx >> 11;
    float c = cs[ss * 64 + pr], si = sn[ss * 64 + pr];
    float2 ri = *(const float2*)&qkv[(size_t)ss * QKVN + hh * HD + 2 * pr];
    float ox = (ri.x * c - ri.y * si) * scale;
    float oy = (ri.x * si + ri.y * c) * scale;
    float hx = bfhi(ox), hy = bfhi(oy);
    size_t w = ((size_t)hh * SEQ + ss) * 64 + pr;
    qh[w] = pack2bf(hx, hy);
    ql[w] = pack2bf(ox - hx, oy - hy);
}

__global__ void rope_k_prep(const float* __restrict__ qkv, const float* __restrict__ cs,
                            const float* __restrict__ sn,
                            uint32_t* __restrict__ kh, uint32_t* __restrict__ kl)
{
    int idx = blockIdx.x * blockDim.x + threadIdx.x;
    if (idx >= SEQ * NKV * 64) return;
    int pr = idx & 63;
    int hh = (idx >> 6) & 7;
    int ss = idx >> 9;
    float c = cs[ss * 64 + pr], si = sn[ss * 64 + pr];
    float2 ri = *(const float2*)&qkv[(size_t)ss * QKVN + DIM + hh * HD + 2 * pr];
    float ox = ri.x * c - ri.y * si;
    float oy = ri.x * si + ri.y * c;
    float hx = bfhi(ox), hy = bfhi(oy);
    size_t w = ((size_t)hh * SEQ + ss) * 64 + pr;
    kh[w] = pack2bf(hx, hy);
    kl[w] = pack2bf(ox - hx, oy - hy);
}

// V transpose: [s][c] fp32 -> [c][s] half2-packed
__global__ void v_prep(const float* __restrict__ qkv, uint32_t* __restrict__ vt)
{
    __shared__ float t[32][33];
    int s0 = blockIdx.x * 32, c0 = blockIdx.y * 32;
    int tx = threadIdx.x, ty = threadIdx.y;
#pragma unroll
    for (int j = 0; j < 32; j += 8)
        t[ty + j][tx] = qkv[(size_t)(s0 + ty + j) * QKVN + DIM + 1024 + c0 + tx];
    __syncthreads();
    if (tx < 16) {
#pragma unroll
        for (int j = 0; j < 32; j += 8)
            vt[(size_t)(c0 + ty + j) * (SEQ / 2) + (s0 >> 1) + tx] =
                pack2h(t[2 * tx][ty + j], t[2 * tx + 1][ty + j]);
    }
}

// ---------------- Flash attention: R10 base + fp16 PV (R7-validated) -------------
// smem words: QH 128x68 | QL 128x68 | KH 2x64x68 | KL 2x64x68 | VT 128x36 | PS 128x36
#define AQH 0
#define AQL 8704
#define AKH 17408
#define AKL 26112
#define KSTG 4352
#define AVT 34816
#define APS 39424
#define ATT_WORDS 44032    // 176128 bytes

__global__ __launch_bounds__(256, 1) void attn_tc(const uint32_t* __restrict__ qh,
                                                  const uint32_t* __restrict__ ql,
                                                  const uint32_t* __restrict__ kh,
                                                  const uint32_t* __restrict__ kl,
                                                  const uint32_t* __restrict__ vt,
                                                  float* __restrict__ O)
{
    extern __shared__ float sm[];
    uint32_t* smw = (uint32_t*)sm;
    int tid = threadIdx.x, wid = tid >> 5, lane = tid & 31;
    int qt = (int)gridDim.x - 1 - (int)blockIdx.x;   // longest-first
    int h = blockIdx.y, kvh = h >> 2;
    int qm0 = qt * 128;
    int g = lane >> 2, tg = lane & 3;
    int wr0 = wid * 16;
    int row0 = qm0 + wr0 + g, row1 = row0 + 8;

    uint32_t shb = (uint32_t)__cvta_generic_to_shared(sm);

    // ---- prologue: issue Q tile + K tile 0 ----
    {
        const uint32_t* qsrc_h = qh + ((size_t)h * SEQ + qm0) * 64;
        const uint32_t* qsrc_l = ql + ((size_t)h * SEQ + qm0) * 64;
        for (int i = tid; i < 2048; i += 256) {
            int r = i >> 4, ch = (i & 15) * 4;
            asm volatile("cp.async.cg.shared.global [%0], [%1], 16;"
                         :: "r"(shb + ((AQH + r * 68 + ch) << 2)), "l"(qsrc_h + r * 64 + ch));
            asm volatile("cp.async.cg.shared.global [%0], [%1], 16;"
                         :: "r"(shb + ((AQL + r * 68 + ch) << 2)), "l"(qsrc_l + r * 64 + ch));
        }
        const uint32_t* ksrc_h = kh + (size_t)kvh * SEQ * 64;
        const uint32_t* ksrc_l = kl + (size_t)kvh * SEQ * 64;
        for (int i = tid; i < 1024; i += 256) {
            int r = i >> 4, ch = (i & 15) * 4;
            asm volatile("cp.async.cg.shared.global [%0], [%1], 16;"
                         :: "r"(shb + ((AKH + r * 68 + ch) << 2)), "l"(ksrc_h + r * 64 + ch));
            asm volatile("cp.async.cg.shared.global [%0], [%1], 16;"
                         :: "r"(shb + ((AKL + r * 68 + ch) << 2)), "l"(ksrc_l + r * 64 + ch));
        }
        asm volatile("cp.async.commit_group;");
    }

    int la = lane & 15, hiq = lane >> 4;
    uint32_t aQH = shb + (uint32_t)((AQH + (wr0 + la) * 68 + hiq * 4) << 2);
    uint32_t aQL = shb + (uint32_t)((AQL + (wr0 + la) * 68 + hiq * 4) << 2);
    uint32_t bKHb = shb + (uint32_t)((AKH + la * 68 + hiq * 4) << 2);
    uint32_t bKLb = shb + (uint32_t)((AKL + la * 68 + hiq * 4) << 2);
    uint32_t aP  = shb + (uint32_t)((APS + (wr0 + la) * 36 + hiq * 4) << 2);
    uint32_t bV  = shb + (uint32_t)((AVT + la * 36 + hiq * 4) << 2);

    float oa[16][4];
#pragma unroll
    for (int i = 0; i < 16; i++)
#pragma unroll
        for (int j = 0; j < 4; j++) oa[i][j] = 0.0f;
    float m0 = -1e30f, m1 = -1e30f, l0 = 0.0f, l1 = 0.0f;

    int ktmax = 2 * qt + 1;
    const uint32_t* ksrc_h = kh + (size_t)kvh * SEQ * 64;
    const uint32_t* ksrc_l = kl + (size_t)kvh * SEQ * 64;
    const uint32_t* vsrc   = vt + (size_t)kvh * HD * (SEQ / 2);

    for (int kt = 0; kt <= ktmax; kt++) {
        int kn0 = kt * 64;
        int st = kt & 1;
        uint32_t stoff = (uint32_t)(st * KSTG * 4);

        __syncthreads();   // V buffer + next K stage free

        // issue V(kt): 128 rows (c) x 32 uint32 (64 seq halfs)
        for (int i = tid; i < 1024; i += 256) {
            int c = i >> 3, ch = (i & 7) * 4;
            asm volatile("cp.async.cg.shared.global [%0], [%1], 16;"
                         :: "r"(shb + ((AVT + c * 36 + ch) << 2)),
                            "l"(vsrc + (size_t)c * (SEQ / 2) + (kn0 >> 1) + ch));
        }
        asm volatile("cp.async.commit_group;");

        if (kt < ktmax) {
            uint32_t nstoff = (uint32_t)((st ^ 1) * KSTG * 4);
            int kn1 = kn0 + 64;
            for (int i = tid; i < 1024; i += 256) {
                int r = i >> 4, ch = (i & 15) * 4;
                asm volatile("cp.async.cg.shared.global [%0], [%1], 16;"
                             :: "r"(shb + ((AKH + r * 68 + ch) << 2) + nstoff),
                                "l"(ksrc_h + (size_t)(kn1 + r) * 64 + ch));
                asm volatile("cp.async.cg.shared.global [%0], [%1], 16;"
                             :: "r"(shb + ((AKL + r * 68 + ch) << 2) + nstoff),
                                "l"(ksrc_l + (size_t)(kn1 + r) * 64 + ch));
            }
        }
        asm volatile("cp.async.commit_group;");

        asm volatile("cp.async.wait_group 2;");   // K(kt) (and Q) ready
        __syncthreads();

        bool skip = (qm0 + wr0 + 15 < kn0);
        float sc[8][4];

        if (!skip) {
            // ---- QK^T: bf16 hi/lo 3-term ----
#pragma unroll
            for (int i = 0; i < 8; i++)
#pragma unroll
                for (int j = 0; j < 4; j++) sc[i][j] = 0.0f;

#pragma unroll 2
            for (int ks = 0; ks < 8; ks++) {
                uint32_t ah[4], al[4];
                ldm4(ah, aQH + ks * 32);
                ldm4(al, aQL + ks * 32);
#pragma unroll
                for (int npp = 0; npp < 4; npp++) {
                    uint32_t bh[4], bl[4];
                    ldm4(bh, bKHb + stoff + (uint32_t)(npp * 16 * 68 * 4) + ks * 32);
                    ldm4(bl, bKLb + stoff + (uint32_t)(npp * 16 * 68 * 4) + ks * 32);
                    mma16(sc[2 * npp],     ah, bh[0], bh[2]);
                    mma16(sc[2 * npp],     al, bh[0], bh[2]);
                    mma16(sc[2 * npp],     ah, bl[0], bl[2]);
                    mma16(sc[2 * npp + 1], ah, bh[1], bh[3]);
                    mma16(sc[2 * npp + 1], al, bh[1], bh[3]);
                    mma16(sc[2 * npp + 1], ah, bl[1], bl[3]);
                }
            }

            if (kt >= 2 * qt) {
#pragma unroll
                for (int nf = 0; nf < 8; nf++) {
                    int kc = kn0 + nf * 8 + 2 * tg;
                    if (kc > row0)     sc[nf][0] = -1e30f;
                    if (kc + 1 > row0) sc[nf][1] = -1e30f;
                    if (kc > row1)     sc[nf][2] = -1e30f;
                    if (kc + 1 > row1) sc[nf][3] = -1e30f;
                }
            }

            float rm0 = -1e30f, rm1 = -1e30f;
#pragma unroll
            for (int nf = 0; nf < 8; nf++) {
                rm0 = fmaxf(rm0, fmaxf(sc[nf][0], sc[nf][1]));
                rm1 = fmaxf(rm1, fmaxf(sc[nf][2], sc[nf][3]));
            }
            rm0 = fmaxf(rm0, __shfl_xor_sync(0xffffffffu, rm0, 1));
            rm0 = fmaxf(rm0, __shfl_xor_sync(0xffffffffu, rm0, 2));
            rm1 = fmaxf(rm1, __shfl_xor_sync(0xffffffffu, rm1, 1));
            rm1 = fmaxf(rm1, __shfl_xor_sync(0xffffffffu, rm1, 2));
            float mn0 = fmaxf(m0, rm0), mn1 = fmaxf(m1, rm1);
            float fac0 = __expf(m0 - mn0), fac1 = __expf(m1 - mn1);
            float rs0 = 0.0f, rs1 = 0.0f;
#pragma unroll
            for (int nf = 0; nf < 8; nf++) {
                sc[nf][0] = __expf(sc[nf][0] - mn0);
                sc[nf][1] = __expf(sc[nf][1] - mn0);
                sc[nf][2] = __expf(sc[nf][2] - mn1);
                sc[nf][3] = __expf(sc[nf][3] - mn1);
                rs0 += sc[nf][0] + sc[nf][1];
                rs1 += sc[nf][2] + sc[nf][3];
            }
            rs0 += __shfl_xor_sync(0xffffffffu, rs0, 1);
            rs0 += __shfl_xor_sync(0xffffffffu, rs0, 2);
            rs1 += __shfl_xor_sync(0xffffffffu, rs1, 1);
            rs1 += __shfl_xor_sync(0xffffffffu, rs1, 2);
            l0 = l0 * fac0 + rs0; m0 = mn0;
            l1 = l1 * fac1 + rs1; m1 = mn1;
#pragma unroll
            for (int nf = 0; nf < 16; nf++) {
                oa[nf][0] *= fac0; oa[nf][1] *= fac0;
                oa[nf][2] *= fac1; oa[nf][3] *= fac1;
            }
        }

        asm volatile("cp.async.wait_group 1;");   // V(kt) ready
        __syncthreads();

        if (!skip) {
            // write P (fp16 packed) to warp-private smem rows
#pragma unroll
            for (int nf = 0; nf < 8; nf++) {
                smw[APS + (wr0 + g) * 36 + nf * 4 + tg]     = pack2h(sc[nf][0], sc[nf][1]);
                smw[APS + (wr0 + g + 8) * 36 + nf * 4 + tg] = pack2h(sc[nf][2], sc[nf][3]);
            }
            __syncwarp();

            // ---- O += P @ V (fp16) ----
#pragma unroll
            for (int ks2 = 0; ks2 < 4; ks2++) {
                uint32_t pa[4];
                ldm4(pa, aP + ks2 * 32);
#pragma unroll
                for (int np = 0; np < 8; np++) {
                    uint32_t bv[4];
                    ldm4(bv, bV + (uint32_t)(np * 16 * 36 * 4) + ks2 * 32);
                    mma16h(oa[2 * np],     pa, bv[0], bv[2]);
                    mma16h(oa[2 * np + 1], pa, bv[1], bv[3]);
                }
            }
        }
    }

    // epilogue: rna-rounded att (O-proj A operand is pre-rounded)
    float inv0 = 1.0f / l0, inv1 = 1.0f / l1;
#pragma unroll
    for (int nf = 0; nf < 16; nf++) {
        int col = nf * 8 + 2 * tg;
        *(float2*)&O[((size_t)row0 * NH + h) * HD + col] =
            make_float2(tf32f(oa[nf][0] * inv0), tf32f(oa[nf][1] * inv0));
        *(float2*)&O[((size_t)row1 * NH + h) * HD + col] =
            make_float2(tf32f(oa[nf][2] * inv1), tf32f(oa[nf][3] * inv1));
    }
}

// ---------------- launch ----------------
extern "C" void kernel_launch(void* const* d_in, const int* in_sizes, int n_in,
                              void* d_out, int out_size)
{
    const float* x  = (const float*)d_in[0];
    const float* wq = (const float*)d_in[1];
    const float* wk = (const float*)d_in[2];
    const float* wv = (const float*)d_in[3];
    const float* wo = (const float*)d_in[4];
    const float* fc = (const float*)d_in[5];
    const float* fs = (const float*)d_in[6];
    float* out = (float*)d_out;

    float *qkv, *att, *xc, *wqc, *wkc, *wvc, *woc;
    uint32_t *qhb, *qlb, *khb, *klb, *vtb;
    cudaGetSymbolAddress((void**)&qkv, g_qkv);
    cudaGetSymbolAddress((void**)&att, g_att);
    cudaGetSymbolAddress((void**)&xc,  g_xc);
    cudaGetSymbolAddress((void**)&wqc, g_wqc);
    cudaGetSymbolAddress((void**)&wkc, g_wkc);
    cudaGetSymbolAddress((void**)&wvc, g_wvc);
    cudaGetSymbolAddress((void**)&woc, g_woc);
    cudaGetSymbolAddress((void**)&qhb, g_qh);
    cudaGetSymbolAddress((void**)&qlb, g_ql);
    cudaGetSymbolAddress((void**)&khb, g_kh);
    cudaGetSymbolAddress((void**)&klb, g_kl);
    cudaGetSymbolAddress((void**)&vtb, g_vt);

    int t = 256;
    // rna prepasses with MLP=4 (all sizes divisible by 4096)
    cvt_rna<<<SEQ * DIM / 4 / 4 / t, t>>>(x, xc, SEQ * DIM / 4);
    cvt_rna<<<DIM * DIM / 4 / 4 / t, t>>>(wq, wqc, DIM * DIM / 4);
    cvt_rna<<<1024 * DIM / 4 / 4 / t, t>>>(wk, wkc, 1024 * DIM / 4);
    cvt_rna<<<1024 * DIM / 4 / 4 / t, t>>>(wv, wvc, 1024 * DIM / 4);
    cvt_rna<<<DIM * DIM / 4 / 4 / t, t>>>(wo, woc, DIM * DIM / 4);

    cudaFuncSetAttribute(gemm_tf32, cudaFuncAttributeMaxDynamicSharedMemorySize, GSMEM_BYTES);

    dim3 blk(256);
    gemm_tf32<<<dim3(QKVN / 256, SEQ / 128), blk, GSMEM_BYTES>>>(xc, wqc, wkc, wvc, qkv, SEQ, QKVN, DIM);

    rope_q_prep<<<(SEQ * NH * 64 + 255) / 256, 256>>>(qkv, fc, fs, qhb, qlb);
    rope_k_prep<<<(SEQ * NKV * 64 + 255) / 256, 256>>>(qkv, fc, fs, khb, klb);
    v_prep<<<dim3(SEQ / 32, 1024 / 32), dim3(32, 8)>>>(qkv, vtb);

    int ash = ATT_WORDS * (int)sizeof(float);
    cudaFuncSetAttribute(attn_tc, cudaFuncAttributeMaxDynamicSharedMemorySize, ash);
    attn_tc<<<dim3(SEQ / 128, NH), blk, ash>>>(qhb, qlb, khb, klb, vtb, att);

    gemm_tf32<<<dim3(DIM / 256, SEQ / 128), blk, GSMEM_BYTES>>>(att, woc, woc, woc, out, SEQ, DIM, DIM);
}